// round 1
// baseline (speedup 1.0000x reference)
#include <cuda_runtime.h>

// SphConv3 fused pipeline, fp32 SIMT baseline.
// Stages:
//   k_down : _x = x @ W_down + b_down                      [N,64]
//   k_zero : clear 9-channel accumulator                   [N,9,64]
//   k_edge : l0 = _x[j]*rbf*factor; red.v4 scatter to agg  (agg0 / sph_v1*3 / sph_v0*5)
//   k_up   : node = [ (v0@W0+b), sum_c (v1c@W1)^2, sum_c (vhc@Wh)^2 ]  [N,384]
//   k_mlp  : out = silu(LN(node@Wn1+b))@Wn2 + b + x        [N,256]

#define N_MAX 26000

__device__ float g_x[(size_t)N_MAX * 64];
__device__ float g_agg[(size_t)N_MAX * 576];   // [N][9][64]
__device__ float g_node[(size_t)N_MAX * 384];

static __device__ __forceinline__ void red4(float* a, float4 v) {
    asm volatile("red.global.add.v4.f32 [%0], {%1,%2,%3,%4};"
                 :: "l"(a), "f"(v.x), "f"(v.y), "f"(v.z), "f"(v.w) : "memory");
}
static __device__ __forceinline__ float4 f4fma(float s, float4 w, float4 acc) {
    acc.x = fmaf(s, w.x, acc.x); acc.y = fmaf(s, w.y, acc.y);
    acc.z = fmaf(s, w.z, acc.z); acc.w = fmaf(s, w.w, acc.w);
    return acc;
}
static __device__ __forceinline__ float4 f4sqacc(float4 s, float4 acc) {
    acc.x = fmaf(s.x, s.x, acc.x); acc.y = fmaf(s.y, s.y, acc.y);
    acc.z = fmaf(s.z, s.z, acc.z); acc.w = fmaf(s.w, s.w, acc.w);
    return acc;
}

// ---------------------------------------------------------------------------
__global__ void k_zero(int n4) {
    int i = blockIdx.x * blockDim.x + threadIdx.x;
    if (i < n4) ((float4*)g_agg)[i] = make_float4(0.f, 0.f, 0.f, 0.f);
}

// ---------------------------------------------------------------------------
// _x = x @ W_down + b_down.  16 rows/block, 256 thr: 16 colgroups x 16 rows.
__global__ void k_down(const float* __restrict__ x, const float* __restrict__ Wd,
                       const float* __restrict__ bd, int N) {
    __shared__ float sX[16 * 256];
    int t = threadIdx.x;
    int row0 = blockIdx.x * 16;
    const float4* x4 = (const float4*)x + (size_t)row0 * 64;
    int lim = (N - row0) * 64;   // valid float4 count
    for (int idx = t; idx < 1024; idx += 256)
        ((float4*)sX)[idx] = (idx < lim) ? x4[idx] : make_float4(0.f, 0.f, 0.f, 0.f);
    __syncthreads();
    int cg = t & 15, rl = t >> 4;
    int row = row0 + rl;
    if (row >= N) return;
    float4 acc = *(const float4*)(bd + cg * 4);
    const float* xr = sX + rl * 256;
#pragma unroll 8
    for (int k = 0; k < 256; k++) {
        float4 w = __ldg((const float4*)(Wd + k * 64) + cg);
        acc = f4fma(xr[k], w, acc);
    }
    *(float4*)(g_x + (size_t)row * 64 + cg * 4) = acc;
}

// ---------------------------------------------------------------------------
// 16 threads per edge (float4 over P=64), 16 edges per block.
__global__ void k_edge(const float* __restrict__ rbf, const float* __restrict__ factor,
                       const float* __restrict__ sph0, const float* __restrict__ sph1,
                       const int* __restrict__ jv, const int* __restrict__ iv, int E) {
    int t = threadIdx.x;
    int lane = t & 15;
    int e = blockIdx.x * 16 + (t >> 4);
    if (e >= E) return;
    int j = __ldg(jv + e), i = __ldg(iv + e);
    float f = __ldg(factor + e);
    float4 xj = *(const float4*)(g_x + (size_t)j * 64 + lane * 4);
    float4 rb = __ldg((const float4*)(rbf + (size_t)e * 64) + lane);
    float4 l0;
    l0.x = xj.x * rb.x * f; l0.y = xj.y * rb.y * f;
    l0.z = xj.z * rb.z * f; l0.w = xj.w * rb.w * f;
    float* base = g_agg + (size_t)i * 576 + lane * 4;
    red4(base, l0);
#pragma unroll
    for (int c = 0; c < 3; c++) {
        float s = __ldg(sph1 + (size_t)e * 3 + c);
        red4(base + (1 + c) * 64, make_float4(l0.x * s, l0.y * s, l0.z * s, l0.w * s));
    }
#pragma unroll
    for (int c = 0; c < 5; c++) {
        float s = __ldg(sph0 + (size_t)e * 5 + c);
        red4(base + (4 + c) * 64, make_float4(l0.x * s, l0.y * s, l0.z * s, l0.w * s));
    }
}

// ---------------------------------------------------------------------------
// Up-projection. 16 nodes/block. Weights (3 x [64,128]) in smem, v = _x*agg in smem.
// Thread: 32 colgroups (4 cols each) x 8 node lanes; handles 2 nodes (W reuse).
__global__ void k_up(const float* __restrict__ W0, const float* __restrict__ b0,
                     const float* __restrict__ W1, const float* __restrict__ Wh, int N) {
    extern __shared__ float sm[];
    float* sW0 = sm;              // 8192
    float* sW1 = sm + 8192;       // 8192
    float* sWh = sm + 16384;      // 8192
    float* sV  = sm + 24576;      // 16*576 = 9216
    float* sX2 = sm + 33792;      // 16*64  = 1024
    int t = threadIdx.x;
    int gn0 = blockIdx.x * 16;

    for (int idx = t; idx < 2048; idx += 256) {
        ((float4*)sW0)[idx] = __ldg((const float4*)W0 + idx);
        ((float4*)sW1)[idx] = __ldg((const float4*)W1 + idx);
        ((float4*)sWh)[idx] = __ldg((const float4*)Wh + idx);
    }
    {
        int limx = (N - gn0) * 16;
        const float4* gx = (const float4*)g_x + (size_t)gn0 * 16;
        ((float4*)sX2)[t & 255] = (t < 256 && t < limx) ? gx[t] : make_float4(0.f, 0.f, 0.f, 0.f);
    }
    __syncthreads();
    {
        int limv = (N - gn0) * 144;
        const float4* ga = (const float4*)g_agg + (size_t)gn0 * 144;
        for (int idx = t; idx < 2304; idx += 256) {
            float4 v = (idx < limv) ? ga[idx] : make_float4(0.f, 0.f, 0.f, 0.f);
            int n = idx / 144;
            int p4 = (idx - n * 144) & 15;
            float4 xv = ((float4*)sX2)[n * 16 + p4];
            v.x *= xv.x; v.y *= xv.y; v.z *= xv.z; v.w *= xv.w;
            ((float4*)sV)[idx] = v;
        }
    }
    __syncthreads();

    int cg = t & 31;
    int nl = t >> 5;
    const float* Va = sV + nl * 576;
    const float* Vb = sV + (nl + 8) * 576;
    const float4* w0 = (const float4*)sW0;
    const float4* w1 = (const float4*)sW1;
    const float4* wh = (const float4*)sWh;

    float4 bv = __ldg((const float4*)b0 + cg);
    float4 a0 = bv, c0 = bv;
#pragma unroll 8
    for (int p = 0; p < 64; p++) {
        float4 w = w0[p * 32 + cg];
        a0 = f4fma(Va[p], w, a0);
        c0 = f4fma(Vb[p], w, c0);
    }
    float4 a1 = make_float4(0.f, 0.f, 0.f, 0.f), c1 = a1;
#pragma unroll
    for (int c = 0; c < 3; c++) {
        float4 sa = make_float4(0.f, 0.f, 0.f, 0.f), sb = sa;
        const float* va = Va + (1 + c) * 64;
        const float* vb = Vb + (1 + c) * 64;
#pragma unroll 8
        for (int p = 0; p < 64; p++) {
            float4 w = w1[p * 32 + cg];
            sa = f4fma(va[p], w, sa);
            sb = f4fma(vb[p], w, sb);
        }
        a1 = f4sqacc(sa, a1); c1 = f4sqacc(sb, c1);
    }
    float4 ah = make_float4(0.f, 0.f, 0.f, 0.f), ch = ah;
#pragma unroll
    for (int c = 0; c < 5; c++) {
        float4 sa = make_float4(0.f, 0.f, 0.f, 0.f), sb = sa;
        const float* va = Va + (4 + c) * 64;
        const float* vb = Vb + (4 + c) * 64;
#pragma unroll 8
        for (int p = 0; p < 64; p++) {
            float4 w = wh[p * 32 + cg];
            sa = f4fma(va[p], w, sa);
            sb = f4fma(vb[p], w, sb);
        }
        ah = f4sqacc(sa, ah); ch = f4sqacc(sb, ch);
    }
    int na = gn0 + nl, nb = na + 8;
    if (na < N) {
        float* o = g_node + (size_t)na * 384;
        ((float4*)o)[cg] = a0; ((float4*)(o + 128))[cg] = a1; ((float4*)(o + 256))[cg] = ah;
    }
    if (nb < N) {
        float* o = g_node + (size_t)nb * 384;
        ((float4*)o)[cg] = c0; ((float4*)(o + 128))[cg] = c1; ((float4*)(o + 256))[cg] = ch;
    }
}

// ---------------------------------------------------------------------------
// MLP: 64 rows/block. GEMM1 (384->256) -> LN+silu -> GEMM2 (256->256) + x.
__global__ void __launch_bounds__(256) k_mlp(
    const float* __restrict__ Wn1, const float* __restrict__ bn1,
    const float* __restrict__ lng, const float* __restrict__ lnb,
    const float* __restrict__ Wn2, const float* __restrict__ bn2,
    const float* __restrict__ x, float* __restrict__ out, int N) {
    extern __shared__ float sm[];
    float* sN = sm;              // 64*384 = 24576
    float* sH = sm + 24576;      // 64*256 = 16384
    int t = threadIdx.x;
    int row0 = blockIdx.x * 64;
    {
        int limv = (N - row0) * 96;
        const float4* gn = (const float4*)g_node + (size_t)row0 * 96;
        for (int idx = t; idx < 6144; idx += 256)
            ((float4*)sN)[idx] = (idx < limv) ? gn[idx] : make_float4(0.f, 0.f, 0.f, 0.f);
    }
    __syncthreads();
    int cg = t & 63;
    int rl = t >> 6;   // 0..3
    float4 acc[16];
    {
        float4 bv = __ldg((const float4*)bn1 + cg);
#pragma unroll
        for (int rr = 0; rr < 16; rr++) acc[rr] = bv;
        for (int k = 0; k < 384; k++) {
            float4 w = __ldg((const float4*)(Wn1 + (size_t)k * 256) + cg);
#pragma unroll
            for (int rr = 0; rr < 16; rr++)
                acc[rr] = f4fma(sN[(rl + rr * 4) * 384 + k], w, acc[rr]);
        }
#pragma unroll
        for (int rr = 0; rr < 16; rr++)
            ((float4*)(sH + (rl + rr * 4) * 256))[cg] = acc[rr];
    }
    __syncthreads();
    {   // LayerNorm + SiLU: 8 warps x 8 rows, warp-per-row reduce
        int w = t >> 5, lane = t & 31;
        for (int rr = 0; rr < 8; rr++) {
            int r = w * 8 + rr;
            float* hr = sH + r * 256;
            float s = 0.f, sq = 0.f;
            float vv[8];
#pragma unroll
            for (int k2 = 0; k2 < 8; k2++) {
                float v = hr[lane + 32 * k2];
                vv[k2] = v; s += v; sq = fmaf(v, v, sq);
            }
#pragma unroll
            for (int o = 16; o > 0; o >>= 1) {
                s += __shfl_xor_sync(0xffffffffu, s, o);
                sq += __shfl_xor_sync(0xffffffffu, sq, o);
            }
            float mean = s * (1.f / 256.f);
            float var = sq * (1.f / 256.f) - mean * mean;
            float rstd = rsqrtf(var + 1e-5f);
#pragma unroll
            for (int k2 = 0; k2 < 8; k2++) {
                int col = lane + 32 * k2;
                float y = (vv[k2] - mean) * rstd * __ldg(lng + col) + __ldg(lnb + col);
                hr[col] = y / (1.f + __expf(-y));
            }
        }
    }
    __syncthreads();
    {
        float4 bv = __ldg((const float4*)bn2 + cg);
#pragma unroll
        for (int rr = 0; rr < 16; rr++) acc[rr] = bv;
        for (int k = 0; k < 256; k++) {
            float4 w = __ldg((const float4*)(Wn2 + (size_t)k * 256) + cg);
#pragma unroll
            for (int rr = 0; rr < 16; rr++)
                acc[rr] = f4fma(sH[(rl + rr * 4) * 256 + k], w, acc[rr]);
        }
#pragma unroll
        for (int rr = 0; rr < 16; rr++) {
            int r = row0 + rl + rr * 4;
            if (r < N) {
                float4 xv = __ldg((const float4*)(x + (size_t)r * 256) + cg);
                float4 o = acc[rr];
                o.x += xv.x; o.y += xv.y; o.z += xv.z; o.w += xv.w;
                ((float4*)(out + (size_t)r * 256))[cg] = o;
            }
        }
    }
}

// ---------------------------------------------------------------------------
extern "C" void kernel_launch(void* const* d_in, const int* in_sizes, int n_in,
                              void* d_out, int out_size) {
    const float* x      = (const float*)d_in[0];
    const float* rbf    = (const float*)d_in[1];
    const float* factor = (const float*)d_in[2];
    const float* sph0   = (const float*)d_in[3];   // (E,5,1)
    const float* sph1   = (const float*)d_in[4];   // (E,3,1)
    const float* Wd     = (const float*)d_in[5];
    const float* bd     = (const float*)d_in[6];
    const float* Wu0    = (const float*)d_in[7];
    const float* bu0    = (const float*)d_in[8];
    const float* Wu1    = (const float*)d_in[9];
    const float* Wuh    = (const float*)d_in[10];
    const float* Wn1    = (const float*)d_in[11];
    const float* bn1    = (const float*)d_in[12];
    const float* lng    = (const float*)d_in[13];
    const float* lnb    = (const float*)d_in[14];
    const float* Wn2    = (const float*)d_in[15];
    const float* bn2    = (const float*)d_in[16];
    const int*   jv     = (const int*)d_in[17];
    const int*   iv     = (const int*)d_in[18];
    float* out = (float*)d_out;

    int N = in_sizes[0] / 256;
    int E = in_sizes[17];

    cudaFuncSetAttribute(k_up,  cudaFuncAttributeMaxDynamicSharedMemorySize, 34816 * 4);
    cudaFuncSetAttribute(k_mlp, cudaFuncAttributeMaxDynamicSharedMemorySize, 40960 * 4);

    k_down<<<(N + 15) / 16, 256>>>(x, Wd, bd, N);
    k_zero<<<(N * 144 + 255) / 256, 256>>>(N * 144);
    k_edge<<<(E + 15) / 16, 256>>>(rbf, factor, sph0, sph1, jv, iv, E);
    k_up<<<(N + 15) / 16, 256, 34816 * 4>>>(Wu0, bu0, Wu1, Wuh, N);
    k_mlp<<<(N + 63) / 64, 256, 40960 * 4>>>(Wn1, bn1, lng, lnb, Wn2, bn2, x, out, N);
}

// round 2
// speedup vs baseline: 1.7914x; 1.7914x over previous
#include <cuda_runtime.h>

// SphConv3 fused pipeline v2.
//   k_down    : _x = x @ W_down + b_down                       [N,64]
//   k_zero_deg/k_hist/k_scan/k_scatter : CSR build + packed edge records
//   k_gather  : per-node register accumulation of 9 channels   [N,9,64]
//   k_up      : node = [(v0@W0+b), sum(v1c@W1)^2, sum(vhc@Wh)^2] [N,384]
//   k_mlp     : out = silu(LN(node@Wn1+b))@Wn2 + b + x          [N,256]

#define N_MAX 26001
#define E_MAX 520001

__device__ float  g_x[(size_t)N_MAX * 64];
__device__ float  g_agg[(size_t)N_MAX * 576];    // [N][9][64]
__device__ float  g_node[(size_t)N_MAX * 384];
__device__ float4 g_pack[(size_t)E_MAX * 3];     // CSR-ordered edge records
__device__ int    g_deg[N_MAX];
__device__ int    g_off[N_MAX + 1];
__device__ int    g_cur[N_MAX];

static __device__ __forceinline__ float4 f4fma(float s, float4 w, float4 acc) {
    acc.x = fmaf(s, w.x, acc.x); acc.y = fmaf(s, w.y, acc.y);
    acc.z = fmaf(s, w.z, acc.z); acc.w = fmaf(s, w.w, acc.w);
    return acc;
}
static __device__ __forceinline__ float4 f4sqacc(float4 s, float4 acc) {
    acc.x = fmaf(s.x, s.x, acc.x); acc.y = fmaf(s.y, s.y, acc.y);
    acc.z = fmaf(s.z, s.z, acc.z); acc.w = fmaf(s.w, s.w, acc.w);
    return acc;
}

// ---------------------------------------------------------------------------
// _x = x @ W_down + b_down.  16 rows/block, 256 thr.
__global__ void k_down(const float* __restrict__ x, const float* __restrict__ Wd,
                       const float* __restrict__ bd, int N) {
    __shared__ float sX[16 * 256];
    int t = threadIdx.x;
    int row0 = blockIdx.x * 16;
    const float4* x4 = (const float4*)x + (size_t)row0 * 64;
    int lim = (N - row0) * 64;
    for (int idx = t; idx < 1024; idx += 256)
        ((float4*)sX)[idx] = (idx < lim) ? x4[idx] : make_float4(0.f, 0.f, 0.f, 0.f);
    __syncthreads();
    int cg = t & 15, rl = t >> 4;
    int row = row0 + rl;
    if (row >= N) return;
    float4 acc = *(const float4*)(bd + cg * 4);
    const float* xr = sX + rl * 256;
#pragma unroll 8
    for (int k = 0; k < 256; k++) {
        float4 w = __ldg((const float4*)(Wd + k * 64) + cg);
        acc = f4fma(xr[k], w, acc);
    }
    *(float4*)(g_x + (size_t)row * 64 + cg * 4) = acc;
}

// ---------------------------------------------------------------------------
__global__ void k_zero_deg(int N) {
    int i = blockIdx.x * blockDim.x + threadIdx.x;
    if (i < N) g_deg[i] = 0;
}

__global__ void k_hist(const int* __restrict__ iv, int E) {
    int e = blockIdx.x * blockDim.x + threadIdx.x;
    if (e < E) atomicAdd(&g_deg[iv[e]], 1);
}

// single-block exclusive scan of g_deg[0..N) -> g_off, g_cur; g_off[N]=total
__global__ void k_scan(int N) {
    __shared__ int sc[1024];
    int t = threadIdx.x;
    int chunk = (N + 1023) >> 10;
    int base = t * chunk;
    int s = 0;
    for (int k = 0; k < chunk; k++) {
        int idx = base + k;
        if (idx < N) s += g_deg[idx];
    }
    sc[t] = s;
    __syncthreads();
#pragma unroll
    for (int off = 1; off < 1024; off <<= 1) {
        int u = (t >= off) ? sc[t - off] : 0;
        __syncthreads();
        sc[t] += u;
        __syncthreads();
    }
    int run = sc[t] - s;   // exclusive base for this chunk
    for (int k = 0; k < chunk; k++) {
        int idx = base + k;
        if (idx < N) {
            g_off[idx] = run;
            g_cur[idx] = run;
            run += g_deg[idx];
        }
    }
    if (t == 1023) g_off[N] = sc[1023];
}

// ticket scatter: write packed edge record at CSR position
__global__ void k_scatter(const int* __restrict__ iv, const int* __restrict__ jv,
                          const float* __restrict__ factor,
                          const float* __restrict__ sph0, const float* __restrict__ sph1,
                          int E) {
    int e = blockIdx.x * blockDim.x + threadIdx.x;
    if (e >= E) return;
    int i = iv[e];
    int pos = atomicAdd(&g_cur[i], 1);
    float4 A, B, C;
    A.x = __int_as_float(jv[e]);
    A.y = __int_as_float(e);
    A.z = __ldg(factor + e);
    A.w = __ldg(sph1 + (size_t)e * 3 + 0);
    B.x = __ldg(sph1 + (size_t)e * 3 + 1);
    B.y = __ldg(sph1 + (size_t)e * 3 + 2);
    B.z = __ldg(sph0 + (size_t)e * 5 + 0);
    B.w = __ldg(sph0 + (size_t)e * 5 + 1);
    C.x = __ldg(sph0 + (size_t)e * 5 + 2);
    C.y = __ldg(sph0 + (size_t)e * 5 + 3);
    C.z = __ldg(sph0 + (size_t)e * 5 + 4);
    C.w = 0.f;
    g_pack[(size_t)pos * 3 + 0] = A;
    g_pack[(size_t)pos * 3 + 1] = B;
    g_pack[(size_t)pos * 3 + 2] = C;
}

// ---------------------------------------------------------------------------
// gather: warp per node, lane owns cols {2*lane, 2*lane+1}, 9 channels in regs
__global__ void __launch_bounds__(256) k_gather(const float* __restrict__ rbf, int N) {
    int w = (blockIdx.x * blockDim.x + threadIdx.x) >> 5;
    if (w >= N) return;
    int lane = threadIdx.x & 31;
    float2 acc[9];
#pragma unroll
    for (int c = 0; c < 9; c++) acc[c] = make_float2(0.f, 0.f);
    int s = g_off[w], eend = g_off[w + 1];
    for (int k = s; k < eend; k++) {
        float4 A = g_pack[(size_t)k * 3 + 0];
        float4 B = g_pack[(size_t)k * 3 + 1];
        float4 C = g_pack[(size_t)k * 3 + 2];
        int j = __float_as_int(A.x);
        int e = __float_as_int(A.y);
        float2 xj = *(const float2*)(g_x + (size_t)j * 64 + lane * 2);
        float2 rb = __ldg((const float2*)(rbf + (size_t)e * 64) + lane);
        float l0x = xj.x * rb.x * A.z;
        float l0y = xj.y * rb.y * A.z;
        acc[0].x += l0x;                      acc[0].y += l0y;
        acc[1].x = fmaf(A.w, l0x, acc[1].x);  acc[1].y = fmaf(A.w, l0y, acc[1].y);
        acc[2].x = fmaf(B.x, l0x, acc[2].x);  acc[2].y = fmaf(B.x, l0y, acc[2].y);
        acc[3].x = fmaf(B.y, l0x, acc[3].x);  acc[3].y = fmaf(B.y, l0y, acc[3].y);
        acc[4].x = fmaf(B.z, l0x, acc[4].x);  acc[4].y = fmaf(B.z, l0y, acc[4].y);
        acc[5].x = fmaf(B.w, l0x, acc[5].x);  acc[5].y = fmaf(B.w, l0y, acc[5].y);
        acc[6].x = fmaf(C.x, l0x, acc[6].x);  acc[6].y = fmaf(C.x, l0y, acc[6].y);
        acc[7].x = fmaf(C.y, l0x, acc[7].x);  acc[7].y = fmaf(C.y, l0y, acc[7].y);
        acc[8].x = fmaf(C.z, l0x, acc[8].x);  acc[8].y = fmaf(C.z, l0y, acc[8].y);
    }
    float* base = g_agg + (size_t)w * 576 + lane * 2;
#pragma unroll
    for (int c = 0; c < 9; c++)
        *(float2*)(base + c * 64) = acc[c];
}

// ---------------------------------------------------------------------------
// k_up: blockIdx.y = matrix m (0:W0+bias, 1:W1 sq, 2:Wh sq). 64 nodes/block.
// smem: W 32KB + V(one channel) 16KB. thread: 8 nodes x 4 cols (float4).
__global__ void __launch_bounds__(256) k_up(
    const float* __restrict__ W0, const float* __restrict__ b0,
    const float* __restrict__ W1, const float* __restrict__ Wh, int N) {
    extern __shared__ float sm[];
    float* sW = sm;          // 8192 floats
    float* sV = sm + 8192;   // 4096 floats
    int t = threadIdx.x;
    int m = blockIdx.y;
    int tile0 = blockIdx.x * 64;

    const float* W = (m == 0) ? W0 : (m == 1) ? W1 : Wh;
    int chBase = (m == 0) ? 0 : (m == 1) ? 1 : 4;
    int nch    = (m == 0) ? 1 : (m == 1) ? 3 : 5;

    for (int idx = t; idx < 2048; idx += 256)
        ((float4*)sW)[idx] = __ldg((const float4*)W + idx);

    int cg = t & 31;
    int wr = t >> 5;
    float4 facc[8];
#pragma unroll
    for (int rr = 0; rr < 8; rr++) facc[rr] = make_float4(0.f, 0.f, 0.f, 0.f);

    for (int ch = 0; ch < nch; ch++) {
        __syncthreads();
        // fill V tile: v = _x * agg[chBase+ch]
        for (int idx = t; idx < 1024; idx += 256) {
            int nl = idx >> 4, k4 = idx & 15;
            int n = tile0 + nl;
            float4 v = make_float4(0.f, 0.f, 0.f, 0.f);
            if (n < N) {
                float4 a  = ((const float4*)g_agg)[(size_t)n * 144 + (chBase + ch) * 16 + k4];
                float4 xv = ((const float4*)g_x)[(size_t)n * 16 + k4];
                v.x = a.x * xv.x; v.y = a.y * xv.y; v.z = a.z * xv.z; v.w = a.w * xv.w;
            }
            ((float4*)sV)[idx] = v;
        }
        __syncthreads();

        float4 cacc[8];
#pragma unroll
        for (int rr = 0; rr < 8; rr++) cacc[rr] = make_float4(0.f, 0.f, 0.f, 0.f);
#pragma unroll 4
        for (int k = 0; k < 64; k++) {
            float4 wv = ((const float4*)sW)[k * 32 + cg];
#pragma unroll
            for (int rr = 0; rr < 8; rr++)
                cacc[rr] = f4fma(sV[(wr * 8 + rr) * 64 + k], wv, cacc[rr]);
        }
        if (m == 0) {
#pragma unroll
            for (int rr = 0; rr < 8; rr++) facc[rr] = cacc[rr];
        } else {
#pragma unroll
            for (int rr = 0; rr < 8; rr++) facc[rr] = f4sqacc(cacc[rr], facc[rr]);
        }
    }

    float4 bv = make_float4(0.f, 0.f, 0.f, 0.f);
    if (m == 0) bv = __ldg((const float4*)b0 + cg);
#pragma unroll
    for (int rr = 0; rr < 8; rr++) {
        int n = tile0 + wr * 8 + rr;
        if (n < N) {
            float4 o = facc[rr];
            o.x += bv.x; o.y += bv.y; o.z += bv.z; o.w += bv.w;
            ((float4*)(g_node + (size_t)n * 384 + m * 128))[cg] = o;
        }
    }
}

// ---------------------------------------------------------------------------
// MLP: 64 rows/block, 512 threads. GEMM1 (384->256) -> LN+silu -> GEMM2 + x.
__global__ void __launch_bounds__(512) k_mlp(
    const float* __restrict__ Wn1, const float* __restrict__ bn1,
    const float* __restrict__ lng, const float* __restrict__ lnb,
    const float* __restrict__ Wn2, const float* __restrict__ bn2,
    const float* __restrict__ x, float* __restrict__ out, int N) {
    extern __shared__ float sm[];
    float* sN = sm;              // 64*384 = 24576
    float* sH = sm + 24576;      // 64*256 = 16384
    int t = threadIdx.x;
    int row0 = blockIdx.x * 64;
    {
        int limv = (N - row0) * 96;
        const float4* gn = (const float4*)g_node + (size_t)row0 * 96;
        for (int idx = t; idx < 6144; idx += 512)
            ((float4*)sN)[idx] = (idx < limv) ? gn[idx] : make_float4(0.f, 0.f, 0.f, 0.f);
    }
    __syncthreads();
    int cg = t & 63;
    int rq = t >> 6;   // 0..7
    float4 acc[8];
    {
        float4 bv = __ldg((const float4*)bn1 + cg);
#pragma unroll
        for (int rr = 0; rr < 8; rr++) acc[rr] = bv;
        for (int k = 0; k < 384; k++) {
            float4 w = __ldg((const float4*)(Wn1 + (size_t)k * 256) + cg);
#pragma unroll
            for (int rr = 0; rr < 8; rr++)
                acc[rr] = f4fma(sN[(rq * 8 + rr) * 384 + k], w, acc[rr]);
        }
#pragma unroll
        for (int rr = 0; rr < 8; rr++)
            ((float4*)(sH + (rq * 8 + rr) * 256))[cg] = acc[rr];
    }
    __syncthreads();
    {   // LayerNorm + SiLU: 16 warps x 4 rows
        int w = t >> 5, lane = t & 31;
#pragma unroll
        for (int rr = 0; rr < 4; rr++) {
            int r = w * 4 + rr;
            float* hr = sH + r * 256;
            float s = 0.f, sq = 0.f;
            float vv[8];
#pragma unroll
            for (int k2 = 0; k2 < 8; k2++) {
                float v = hr[lane + 32 * k2];
                vv[k2] = v; s += v; sq = fmaf(v, v, sq);
            }
#pragma unroll
            for (int o = 16; o > 0; o >>= 1) {
                s  += __shfl_xor_sync(0xffffffffu, s, o);
                sq += __shfl_xor_sync(0xffffffffu, sq, o);
            }
            float mean = s * (1.f / 256.f);
            float var = sq * (1.f / 256.f) - mean * mean;
            float rstd = rsqrtf(var + 1e-5f);
#pragma unroll
            for (int k2 = 0; k2 < 8; k2++) {
                int col = lane + 32 * k2;
                float y = (vv[k2] - mean) * rstd * __ldg(lng + col) + __ldg(lnb + col);
                hr[col] = y / (1.f + __expf(-y));
            }
        }
    }
    __syncthreads();
    {
        float4 bv = __ldg((const float4*)bn2 + cg);
#pragma unroll
        for (int rr = 0; rr < 8; rr++) acc[rr] = bv;
        for (int k = 0; k < 256; k++) {
            float4 w = __ldg((const float4*)(Wn2 + (size_t)k * 256) + cg);
#pragma unroll
            for (int rr = 0; rr < 8; rr++)
                acc[rr] = f4fma(sH[(rq * 8 + rr) * 256 + k], w, acc[rr]);
        }
#pragma unroll
        for (int rr = 0; rr < 8; rr++) {
            int r = row0 + rq * 8 + rr;
            if (r < N) {
                float4 xv = __ldg((const float4*)(x + (size_t)r * 256) + cg);
                float4 o = acc[rr];
                o.x += xv.x; o.y += xv.y; o.z += xv.z; o.w += xv.w;
                ((float4*)(out + (size_t)r * 256))[cg] = o;
            }
        }
    }
}

// ---------------------------------------------------------------------------
extern "C" void kernel_launch(void* const* d_in, const int* in_sizes, int n_in,
                              void* d_out, int out_size) {
    const float* x      = (const float*)d_in[0];
    const float* rbf    = (const float*)d_in[1];
    const float* factor = (const float*)d_in[2];
    const float* sph0   = (const float*)d_in[3];   // (E,5,1)
    const float* sph1   = (const float*)d_in[4];   // (E,3,1)
    const float* Wd     = (const float*)d_in[5];
    const float* bd     = (const float*)d_in[6];
    const float* Wu0    = (const float*)d_in[7];
    const float* bu0    = (const float*)d_in[8];
    const float* Wu1    = (const float*)d_in[9];
    const float* Wuh    = (const float*)d_in[10];
    const float* Wn1    = (const float*)d_in[11];
    const float* bn1    = (const float*)d_in[12];
    const float* lng    = (const float*)d_in[13];
    const float* lnb    = (const float*)d_in[14];
    const float* Wn2    = (const float*)d_in[15];
    const float* bn2    = (const float*)d_in[16];
    const int*   jv     = (const int*)d_in[17];
    const int*   iv     = (const int*)d_in[18];
    float* out = (float*)d_out;

    int N = in_sizes[0] / 256;
    int E = in_sizes[17];

    cudaFuncSetAttribute(k_up,  cudaFuncAttributeMaxDynamicSharedMemorySize, 12288 * 4);
    cudaFuncSetAttribute(k_mlp, cudaFuncAttributeMaxDynamicSharedMemorySize, 40960 * 4);

    k_down<<<(N + 15) / 16, 256>>>(x, Wd, bd, N);
    k_zero_deg<<<(N + 255) / 256, 256>>>(N);
    k_hist<<<(E + 255) / 256, 256>>>(iv, E);
    k_scan<<<1, 1024>>>(N);
    k_scatter<<<(E + 255) / 256, 256>>>(iv, jv, factor, sph0, sph1, E);
    k_gather<<<(N + 7) / 8, 256>>>(rbf, N);
    dim3 upGrid((N + 63) / 64, 3);
    k_up<<<upGrid, 256, 12288 * 4>>>(Wu0, bu0, Wu1, Wuh, N);
    k_mlp<<<(N + 63) / 64, 512, 40960 * 4>>>(Wn1, bn1, lng, lnb, Wn2, bn2, x, out, N);
}

// round 4
// speedup vs baseline: 2.6451x; 1.4766x over previous
#include <cuda_runtime.h>
#include <cstdint>

// SphConv3 fused pipeline v4: mma.sync tf32 MLP (tcgen05 unavailable: harness
// targets sm_103 without the 'a' feature set).
//   k_down    : _x = x @ W_down + b_down                       [N,64]
//   CSR build : k_zero_deg / k_hist / k_scan / k_scatter
//   k_gather  : per-node register accumulation of 9 channels   [N,9,64]
//   k_up      : node = [(v0@W0+b), sum(v1c@W1)^2, sum(vhc@Wh)^2] [N,384]
//   k_mlp_mma : tf32 mma.sync: GEMM1(384->256) -> LN+SiLU -> GEMM2(256->256)+x

#define N_MAX 26001
#define E_MAX 520001

__device__ float  g_x[(size_t)N_MAX * 64];
__device__ float  g_agg[(size_t)N_MAX * 576];    // [N][9][64]
__device__ float  g_node[(size_t)N_MAX * 384];
__device__ float4 g_pack[(size_t)E_MAX * 3];     // CSR-ordered edge records
__device__ int    g_deg[N_MAX];
__device__ int    g_off[N_MAX + 1];
__device__ int    g_cur[N_MAX];

static __device__ __forceinline__ float4 f4fma(float s, float4 w, float4 acc) {
    acc.x = fmaf(s, w.x, acc.x); acc.y = fmaf(s, w.y, acc.y);
    acc.z = fmaf(s, w.z, acc.z); acc.w = fmaf(s, w.w, acc.w);
    return acc;
}
static __device__ __forceinline__ float4 f4sqacc(float4 s, float4 acc) {
    acc.x = fmaf(s.x, s.x, acc.x); acc.y = fmaf(s.y, s.y, acc.y);
    acc.z = fmaf(s.z, s.z, acc.z); acc.w = fmaf(s.w, s.w, acc.w);
    return acc;
}
static __device__ __forceinline__ float tf32r(float x) {
    float r;
    asm("cvt.rna.tf32.f32 %0, %1;" : "=f"(r) : "f"(x));
    return r;
}
static __device__ __forceinline__ float4 tf32r4(float4 v) {
    v.x = tf32r(v.x); v.y = tf32r(v.y); v.z = tf32r(v.z); v.w = tf32r(v.w);
    return v;
}
static __device__ __forceinline__ void mma_tf32(float* c, const uint32_t* a,
                                                uint32_t b0, uint32_t b1) {
    asm volatile(
        "mma.sync.aligned.m16n8k8.row.col.f32.tf32.tf32.f32 "
        "{%0,%1,%2,%3}, {%4,%5,%6,%7}, {%8,%9}, {%0,%1,%2,%3};"
        : "+f"(c[0]), "+f"(c[1]), "+f"(c[2]), "+f"(c[3])
        : "r"(a[0]), "r"(a[1]), "r"(a[2]), "r"(a[3]), "r"(b0), "r"(b1));
}

// ---------------------------------------------------------------------------
// _x = x @ W_down + b_down.  16 rows/block, 256 thr.
__global__ void k_down(const float* __restrict__ x, const float* __restrict__ Wd,
                       const float* __restrict__ bd, int N) {
    __shared__ float sX[16 * 256];
    int t = threadIdx.x;
    int row0 = blockIdx.x * 16;
    const float4* x4 = (const float4*)x + (size_t)row0 * 64;
    int lim = (N - row0) * 64;
    for (int idx = t; idx < 1024; idx += 256)
        ((float4*)sX)[idx] = (idx < lim) ? x4[idx] : make_float4(0.f, 0.f, 0.f, 0.f);
    __syncthreads();
    int cg = t & 15, rl = t >> 4;
    int row = row0 + rl;
    if (row >= N) return;
    float4 acc = *(const float4*)(bd + cg * 4);
    const float* xr = sX + rl * 256;
#pragma unroll 8
    for (int k = 0; k < 256; k++) {
        float4 w = __ldg((const float4*)(Wd + k * 64) + cg);
        acc = f4fma(xr[k], w, acc);
    }
    *(float4*)(g_x + (size_t)row * 64 + cg * 4) = acc;
}

// ---------------------------------------------------------------------------
__global__ void k_zero_deg(int N) {
    int i = blockIdx.x * blockDim.x + threadIdx.x;
    if (i < N) g_deg[i] = 0;
}

__global__ void k_hist(const int* __restrict__ iv, int E) {
    int e = blockIdx.x * blockDim.x + threadIdx.x;
    if (e < E) atomicAdd(&g_deg[iv[e]], 1);
}

// single-block scan, smem-staged
__global__ void k_scan(int N) {
    extern __shared__ int si[];
    int* sDeg = si;
    int* sOff = si + N;
    __shared__ int warpTot[32];
    int t = threadIdx.x;
    for (int idx = t; idx < N; idx += 1024) sDeg[idx] = g_deg[idx];
    __syncthreads();
    int chunk = (N + 1023) >> 10;
    int base = t * chunk;
    int s = 0;
    for (int k = 0; k < chunk; k++) {
        int i = base + k;
        if (i < N) s += sDeg[i];
    }
    int lane = t & 31, w = t >> 5;
    int pre = s;
#pragma unroll
    for (int o = 1; o < 32; o <<= 1) {
        int u = __shfl_up_sync(0xffffffffu, pre, o);
        if (lane >= o) pre += u;
    }
    if (lane == 31) warpTot[w] = pre;
    __syncthreads();
    if (w == 0) {
        int v = warpTot[lane];
#pragma unroll
        for (int o = 1; o < 32; o <<= 1) {
            int u = __shfl_up_sync(0xffffffffu, v, o);
            if (lane >= o) v += u;
        }
        warpTot[lane] = v;
    }
    __syncthreads();
    int excl = pre - s + (w ? warpTot[w - 1] : 0);
    for (int k = 0; k < chunk; k++) {
        int i = base + k;
        if (i < N) { sOff[i] = excl; excl += sDeg[i]; }
    }
    __syncthreads();
    for (int idx = t; idx < N; idx += 1024) {
        int v = sOff[idx];
        g_off[idx] = v;
        g_cur[idx] = v;
    }
    if (t == 1023) g_off[N] = excl;
}

// ticket scatter: packed edge record at CSR position
__global__ void k_scatter(const int* __restrict__ iv, const int* __restrict__ jv,
                          const float* __restrict__ factor,
                          const float* __restrict__ sph0, const float* __restrict__ sph1,
                          int E) {
    int e = blockIdx.x * blockDim.x + threadIdx.x;
    if (e >= E) return;
    int i = iv[e];
    int pos = atomicAdd(&g_cur[i], 1);
    float4 A, B, C;
    A.x = __int_as_float(jv[e]);
    A.y = __int_as_float(e);
    A.z = __ldg(factor + e);
    A.w = __ldg(sph1 + (size_t)e * 3 + 0);
    B.x = __ldg(sph1 + (size_t)e * 3 + 1);
    B.y = __ldg(sph1 + (size_t)e * 3 + 2);
    B.z = __ldg(sph0 + (size_t)e * 5 + 0);
    B.w = __ldg(sph0 + (size_t)e * 5 + 1);
    C.x = __ldg(sph0 + (size_t)e * 5 + 2);
    C.y = __ldg(sph0 + (size_t)e * 5 + 3);
    C.z = __ldg(sph0 + (size_t)e * 5 + 4);
    C.w = 0.f;
    g_pack[(size_t)pos * 3 + 0] = A;
    g_pack[(size_t)pos * 3 + 1] = B;
    g_pack[(size_t)pos * 3 + 2] = C;
}

// ---------------------------------------------------------------------------
// gather: warp per node, lane owns cols {2*lane, 2*lane+1}
__global__ void __launch_bounds__(256) k_gather(const float* __restrict__ rbf, int N) {
    int w = (blockIdx.x * blockDim.x + threadIdx.x) >> 5;
    if (w >= N) return;
    int lane = threadIdx.x & 31;
    float2 acc[9];
#pragma unroll
    for (int c = 0; c < 9; c++) acc[c] = make_float2(0.f, 0.f);
    int s = g_off[w], eend = g_off[w + 1];
    for (int k = s; k < eend; k++) {
        float4 A = g_pack[(size_t)k * 3 + 0];
        float4 B = g_pack[(size_t)k * 3 + 1];
        float4 C = g_pack[(size_t)k * 3 + 2];
        int j = __float_as_int(A.x);
        int e = __float_as_int(A.y);
        float2 xj = *(const float2*)(g_x + (size_t)j * 64 + lane * 2);
        float2 rb = __ldg((const float2*)(rbf + (size_t)e * 64) + lane);
        float l0x = xj.x * rb.x * A.z;
        float l0y = xj.y * rb.y * A.z;
        acc[0].x += l0x;                      acc[0].y += l0y;
        acc[1].x = fmaf(A.w, l0x, acc[1].x);  acc[1].y = fmaf(A.w, l0y, acc[1].y);
        acc[2].x = fmaf(B.x, l0x, acc[2].x);  acc[2].y = fmaf(B.x, l0y, acc[2].y);
        acc[3].x = fmaf(B.y, l0x, acc[3].x);  acc[3].y = fmaf(B.y, l0y, acc[3].y);
        acc[4].x = fmaf(B.z, l0x, acc[4].x);  acc[4].y = fmaf(B.z, l0y, acc[4].y);
        acc[5].x = fmaf(B.w, l0x, acc[5].x);  acc[5].y = fmaf(B.w, l0y, acc[5].y);
        acc[6].x = fmaf(C.x, l0x, acc[6].x);  acc[6].y = fmaf(C.x, l0y, acc[6].y);
        acc[7].x = fmaf(C.y, l0x, acc[7].x);  acc[7].y = fmaf(C.y, l0y, acc[7].y);
        acc[8].x = fmaf(C.z, l0x, acc[8].x);  acc[8].y = fmaf(C.z, l0y, acc[8].y);
    }
    float* base = g_agg + (size_t)w * 576 + lane * 2;
#pragma unroll
    for (int c = 0; c < 9; c++)
        *(float2*)(base + c * 64) = acc[c];
}

// ---------------------------------------------------------------------------
// k_up (SIMT)
__global__ void __launch_bounds__(256) k_up(
    const float* __restrict__ W0, const float* __restrict__ b0,
    const float* __restrict__ W1, const float* __restrict__ Wh, int N) {
    extern __shared__ float sm[];
    float* sW = sm;
    float* sV = sm + 8192;
    int t = threadIdx.x;
    int m = blockIdx.y;
    int tile0 = blockIdx.x * 64;

    const float* W = (m == 0) ? W0 : (m == 1) ? W1 : Wh;
    int chBase = (m == 0) ? 0 : (m == 1) ? 1 : 4;
    int nch    = (m == 0) ? 1 : (m == 1) ? 3 : 5;

    for (int idx = t; idx < 2048; idx += 256)
        ((float4*)sW)[idx] = __ldg((const float4*)W + idx);

    int cg = t & 31;
    int wr = t >> 5;
    float4 facc[8];
#pragma unroll
    for (int rr = 0; rr < 8; rr++) facc[rr] = make_float4(0.f, 0.f, 0.f, 0.f);

    for (int ch = 0; ch < nch; ch++) {
        __syncthreads();
        for (int idx = t; idx < 1024; idx += 256) {
            int nl = idx >> 4, k4 = idx & 15;
            int n = tile0 + nl;
            float4 v = make_float4(0.f, 0.f, 0.f, 0.f);
            if (n < N) {
                float4 a  = ((const float4*)g_agg)[(size_t)n * 144 + (chBase + ch) * 16 + k4];
                float4 xv = ((const float4*)g_x)[(size_t)n * 16 + k4];
                v.x = a.x * xv.x; v.y = a.y * xv.y; v.z = a.z * xv.z; v.w = a.w * xv.w;
            }
            ((float4*)sV)[idx] = v;
        }
        __syncthreads();

        float4 cacc[8];
#pragma unroll
        for (int rr = 0; rr < 8; rr++) cacc[rr] = make_float4(0.f, 0.f, 0.f, 0.f);
#pragma unroll 4
        for (int k = 0; k < 64; k++) {
            float4 wv = ((const float4*)sW)[k * 32 + cg];
#pragma unroll
            for (int rr = 0; rr < 8; rr++)
                cacc[rr] = f4fma(sV[(wr * 8 + rr) * 64 + k], wv, cacc[rr]);
        }
        if (m == 0) {
#pragma unroll
            for (int rr = 0; rr < 8; rr++) facc[rr] = cacc[rr];
        } else {
#pragma unroll
            for (int rr = 0; rr < 8; rr++) facc[rr] = f4sqacc(cacc[rr], facc[rr]);
        }
    }

    float4 bv = make_float4(0.f, 0.f, 0.f, 0.f);
    if (m == 0) bv = __ldg((const float4*)b0 + cg);
#pragma unroll
    for (int rr = 0; rr < 8; rr++) {
        int n = tile0 + wr * 8 + rr;
        if (n < N) {
            float4 o = facc[rr];
            o.x += bv.x; o.y += bv.y; o.z += bv.z; o.w += bv.w;
            ((float4*)(g_node + (size_t)n * 384 + m * 128))[cg] = o;
        }
    }
}

// ---------------------------------------------------------------------------
// k_mlp_mma: tf32 mma.sync. 64 rows/block, 256 thr (8 warps, grid 2m x 4n,
// warp tile 32x64). smem: sN [64][388] (aliased by sH [64][260]) + sW [64][260].
#define SN_S 388
#define SW_S 260
#define SH_S 260
__global__ void __launch_bounds__(256) k_mlp_mma(
    const float* __restrict__ Wn1, const float* __restrict__ bn1,
    const float* __restrict__ lng, const float* __restrict__ lnb,
    const float* __restrict__ Wn2, const float* __restrict__ bn2,
    const float* __restrict__ x, float* __restrict__ out, int N) {
    extern __shared__ float sm[];
    float* sN = sm;                  // 64*388 = 24832 floats
    float* sW = sm + 24832;          // 64*260 = 16640 floats
    float* sH = sm;                  // alias sN after GEMM1
    int t = threadIdx.x, lane = t & 31, wid = t >> 5;
    int wm = wid & 1, wn = wid >> 1;
    int row0 = blockIdx.x * 64;
    int qr = lane >> 2, qc = lane & 3;

    // stage node tile (tf32-rounded)
    for (int idx = t; idx < 64 * 96; idx += 256) {
        int r = idx / 96, c4 = (idx - r * 96) * 4;
        float4 v = tf32r4(*(const float4*)(g_node + (size_t)(row0 + r) * 384 + c4));
        *(float4*)(sN + r * SN_S + c4) = v;
    }

    float acc[2][8][4];
#pragma unroll
    for (int mt = 0; mt < 2; mt++)
#pragma unroll
        for (int nt = 0; nt < 8; nt++)
#pragma unroll
            for (int q = 0; q < 4; q++) acc[mt][nt][q] = 0.f;

    // ---------------- GEMM1: K = 384, 6 chunks of 64
    for (int kc = 0; kc < 6; kc++) {
        __syncthreads();
        for (int idx = t; idx < 64 * 64; idx += 256) {
            int r = idx >> 6, c4 = (idx & 63) * 4;
            float4 v = tf32r4(*(const float4*)(Wn1 + (size_t)(kc * 64 + r) * 256 + c4));
            *(float4*)(sW + r * SW_S + c4) = v;
        }
        __syncthreads();
#pragma unroll
        for (int k8 = 0; k8 < 8; k8++) {
            int kb = kc * 64 + k8 * 8;
            uint32_t a[2][4];
#pragma unroll
            for (int mt = 0; mt < 2; mt++) {
                const uint32_t* p = (const uint32_t*)sN +
                    (wm * 32 + mt * 16 + qr) * SN_S + kb + qc;
                a[mt][0] = p[0]; a[mt][2] = p[4];
                a[mt][1] = p[8 * SN_S]; a[mt][3] = p[8 * SN_S + 4];
            }
#pragma unroll
            for (int nt = 0; nt < 8; nt++) {
                const uint32_t* p = (const uint32_t*)sW +
                    (k8 * 8 + qc) * SW_S + wn * 64 + nt * 8 + qr;
                uint32_t b0 = p[0], b1 = p[4 * SW_S];
                mma_tf32(acc[0][nt], a[0], b0, b1);
                mma_tf32(acc[1][nt], a[1], b0, b1);
            }
        }
    }
    __syncthreads();

    // spill C1 to sH (alias of sN)
#pragma unroll
    for (int mt = 0; mt < 2; mt++)
#pragma unroll
        for (int nt = 0; nt < 8; nt++) {
            int r = wm * 32 + mt * 16 + qr;
            int c = wn * 64 + nt * 8 + qc * 2;
            *(float2*)(sH + r * SH_S + c) = make_float2(acc[mt][nt][0], acc[mt][nt][1]);
            *(float2*)(sH + (r + 8) * SH_S + c) = make_float2(acc[mt][nt][2], acc[mt][nt][3]);
        }
    __syncthreads();

    // LN + SiLU per row (warp per row, 8 rows/warp), tf32-round result in place
#pragma unroll
    for (int rr = 0; rr < 8; rr++) {
        int r = wid * 8 + rr;
        float* hr = sH + r * SH_S;
        float vv[8];
        float s1 = 0.f, s2 = 0.f;
#pragma unroll
        for (int k2 = 0; k2 < 8; k2++) {
            int col = lane + 32 * k2;
            float v = hr[col] + __ldg(bn1 + col);
            vv[k2] = v; s1 += v; s2 = fmaf(v, v, s2);
        }
#pragma unroll
        for (int o = 16; o > 0; o >>= 1) {
            s1 += __shfl_xor_sync(0xffffffffu, s1, o);
            s2 += __shfl_xor_sync(0xffffffffu, s2, o);
        }
        float mean = s1 * (1.f / 256.f);
        float var = s2 * (1.f / 256.f) - mean * mean;
        float rstd = rsqrtf(var + 1e-5f);
#pragma unroll
        for (int k2 = 0; k2 < 8; k2++) {
            int col = lane + 32 * k2;
            float y = (vv[k2] - mean) * rstd * __ldg(lng + col) + __ldg(lnb + col);
            hr[col] = tf32r(y / (1.f + __expf(-y)));
        }
    }
    __syncthreads();

    // ---------------- GEMM2: K = 256, 4 chunks of 64
#pragma unroll
    for (int mt = 0; mt < 2; mt++)
#pragma unroll
        for (int nt = 0; nt < 8; nt++)
#pragma unroll
            for (int q = 0; q < 4; q++) acc[mt][nt][q] = 0.f;

    for (int kc = 0; kc < 4; kc++) {
        __syncthreads();
        for (int idx = t; idx < 64 * 64; idx += 256) {
            int r = idx >> 6, c4 = (idx & 63) * 4;
            float4 v = tf32r4(*(const float4*)(Wn2 + (size_t)(kc * 64 + r) * 256 + c4));
            *(float4*)(sW + r * SW_S + c4) = v;
        }
        __syncthreads();
#pragma unroll
        for (int k8 = 0; k8 < 8; k8++) {
            int kb = kc * 64 + k8 * 8;
            uint32_t a[2][4];
#pragma unroll
            for (int mt = 0; mt < 2; mt++) {
                const uint32_t* p = (const uint32_t*)sH +
                    (wm * 32 + mt * 16 + qr) * SH_S + kb + qc;
                a[mt][0] = p[0]; a[mt][2] = p[4];
                a[mt][1] = p[8 * SH_S]; a[mt][3] = p[8 * SH_S + 4];
            }
#pragma unroll
            for (int nt = 0; nt < 8; nt++) {
                const uint32_t* p = (const uint32_t*)sW +
                    (k8 * 8 + qc) * SW_S + wn * 64 + nt * 8 + qr;
                uint32_t b0 = p[0], b1 = p[4 * SW_S];
                mma_tf32(acc[0][nt], a[0], b0, b1);
                mma_tf32(acc[1][nt], a[1], b0, b1);
            }
        }
    }

    // epilogue: + bn2 + x -> out
#pragma unroll
    for (int mt = 0; mt < 2; mt++) {
        int rl = wm * 32 + mt * 16 + qr;
#pragma unroll
        for (int half = 0; half < 2; half++) {
            int rg = row0 + rl + half * 8;
            if (rg < N) {
#pragma unroll
                for (int nt = 0; nt < 8; nt++) {
                    int c = wn * 64 + nt * 8 + qc * 2;
                    float2 xv = __ldg((const float2*)(x + (size_t)rg * 256 + c));
                    float2 o;
                    o.x = acc[mt][nt][half * 2 + 0] + __ldg(bn2 + c) + xv.x;
                    o.y = acc[mt][nt][half * 2 + 1] + __ldg(bn2 + c + 1) + xv.y;
                    *(float2*)(out + (size_t)rg * 256 + c) = o;
                }
            }
        }
    }
}

// ---------------------------------------------------------------------------
extern "C" void kernel_launch(void* const* d_in, const int* in_sizes, int n_in,
                              void* d_out, int out_size) {
    const float* x      = (const float*)d_in[0];
    const float* rbf    = (const float*)d_in[1];
    const float* factor = (const float*)d_in[2];
    const float* sph0   = (const float*)d_in[3];
    const float* sph1   = (const float*)d_in[4];
    const float* Wd     = (const float*)d_in[5];
    const float* bd     = (const float*)d_in[6];
    const float* Wu0    = (const float*)d_in[7];
    const float* bu0    = (const float*)d_in[8];
    const float* Wu1    = (const float*)d_in[9];
    const float* Wuh    = (const float*)d_in[10];
    const float* Wn1    = (const float*)d_in[11];
    const float* bn1    = (const float*)d_in[12];
    const float* lng    = (const float*)d_in[13];
    const float* lnb    = (const float*)d_in[14];
    const float* Wn2    = (const float*)d_in[15];
    const float* bn2    = (const float*)d_in[16];
    const int*   jv     = (const int*)d_in[17];
    const int*   iv     = (const int*)d_in[18];
    float* out = (float*)d_out;

    int N = in_sizes[0] / 256;
    int E = in_sizes[17];

    int mlpSmem = (24832 + 16640) * 4;   // 165,888 B
    cudaFuncSetAttribute(k_up,      cudaFuncAttributeMaxDynamicSharedMemorySize, 12288 * 4);
    cudaFuncSetAttribute(k_scan,    cudaFuncAttributeMaxDynamicSharedMemorySize, 2 * (N + 4) * 4);
    cudaFuncSetAttribute(k_mlp_mma, cudaFuncAttributeMaxDynamicSharedMemorySize, mlpSmem);

    k_down<<<(N + 15) / 16, 256>>>(x, Wd, bd, N);
    k_zero_deg<<<(N + 255) / 256, 256>>>(N);
    k_hist<<<(E + 255) / 256, 256>>>(iv, E);
    k_scan<<<1, 1024, 2 * (N + 4) * 4>>>(N);
    k_scatter<<<(E + 255) / 256, 256>>>(iv, jv, factor, sph0, sph1, E);
    k_gather<<<(N + 7) / 8, 256>>>(rbf, N);
    dim3 upGrid((N + 63) / 64, 3);
    k_up<<<upGrid, 256, 12288 * 4>>>(Wu0, bu0, Wu1, Wuh, N);
    k_mlp_mma<<<(N + 63) / 64, 256, mlpSmem>>>(Wn1, bn1, lng, lnb, Wn2, bn2, x, out, N);
}

// round 5
// speedup vs baseline: 3.1183x; 1.1789x over previous
#include <cuda_runtime.h>
#include <cstdint>

// SphConv3 fused pipeline v5: mma.sync tf32 for both k_up and k_mlp.
//   k_down    : _x = x @ W_down + b_down                       [N,64]
//   CSR build : k_zero_deg / k_hist / k_scan / k_scatter
//   k_gather  : per-node register accumulation of 9 channels   [N,9,64]
//   k_up_mma  : node = [(v0@W0+b), sum(v1c@W1)^2, sum(vhc@Wh)^2] [N,384]
//   k_mlp_mma : GEMM1(384->256) -> LN+SiLU -> GEMM2(256->256)+x

#define N_MAX 26001
#define E_MAX 520001

__device__ float  g_x[(size_t)N_MAX * 64];
__device__ float  g_agg[(size_t)N_MAX * 576];    // [N][9][64]
__device__ float  g_node[(size_t)N_MAX * 384];
__device__ float4 g_pack[(size_t)E_MAX * 3];     // CSR-ordered edge records
__device__ int    g_deg[N_MAX];
__device__ int    g_off[N_MAX + 1];
__device__ int    g_cur[N_MAX];

static __device__ __forceinline__ float4 f4fma(float s, float4 w, float4 acc) {
    acc.x = fmaf(s, w.x, acc.x); acc.y = fmaf(s, w.y, acc.y);
    acc.z = fmaf(s, w.z, acc.z); acc.w = fmaf(s, w.w, acc.w);
    return acc;
}
static __device__ __forceinline__ float tf32r(float x) {
    float r;
    asm("cvt.rna.tf32.f32 %0, %1;" : "=f"(r) : "f"(x));
    return r;
}
static __device__ __forceinline__ float4 tf32r4(float4 v) {
    v.x = tf32r(v.x); v.y = tf32r(v.y); v.z = tf32r(v.z); v.w = tf32r(v.w);
    return v;
}
static __device__ __forceinline__ void mma_tf32(float* c, const uint32_t* a,
                                                uint32_t b0, uint32_t b1) {
    asm volatile(
        "mma.sync.aligned.m16n8k8.row.col.f32.tf32.tf32.f32 "
        "{%0,%1,%2,%3}, {%4,%5,%6,%7}, {%8,%9}, {%0,%1,%2,%3};"
        : "+f"(c[0]), "+f"(c[1]), "+f"(c[2]), "+f"(c[3])
        : "r"(a[0]), "r"(a[1]), "r"(a[2]), "r"(a[3]), "r"(b0), "r"(b1));
}

// ---------------------------------------------------------------------------
// _x = x @ W_down + b_down.  16 rows/block, 256 thr.
__global__ void k_down(const float* __restrict__ x, const float* __restrict__ Wd,
                       const float* __restrict__ bd, int N) {
    __shared__ float sX[16 * 256];
    int t = threadIdx.x;
    int row0 = blockIdx.x * 16;
    const float4* x4 = (const float4*)x + (size_t)row0 * 64;
    int lim = (N - row0) * 64;
    for (int idx = t; idx < 1024; idx += 256)
        ((float4*)sX)[idx] = (idx < lim) ? x4[idx] : make_float4(0.f, 0.f, 0.f, 0.f);
    __syncthreads();
    int cg = t & 15, rl = t >> 4;
    int row = row0 + rl;
    if (row >= N) return;
    float4 acc = *(const float4*)(bd + cg * 4);
    const float* xr = sX + rl * 256;
#pragma unroll 8
    for (int k = 0; k < 256; k++) {
        float4 w = __ldg((const float4*)(Wd + k * 64) + cg);
        acc = f4fma(xr[k], w, acc);
    }
    *(float4*)(g_x + (size_t)row * 64 + cg * 4) = acc;
}

// ---------------------------------------------------------------------------
__global__ void k_zero_deg(int N) {
    int i = blockIdx.x * blockDim.x + threadIdx.x;
    if (i < N) g_deg[i] = 0;
}

__global__ void k_hist(const int* __restrict__ iv, int E) {
    int e = blockIdx.x * blockDim.x + threadIdx.x;
    if (e < E) atomicAdd(&g_deg[iv[e]], 1);
}

// single-block scan, smem-staged
__global__ void k_scan(int N) {
    extern __shared__ int si[];
    int* sDeg = si;
    int* sOff = si + N;
    __shared__ int warpTot[32];
    int t = threadIdx.x;
    for (int idx = t; idx < N; idx += 1024) sDeg[idx] = g_deg[idx];
    __syncthreads();
    int chunk = (N + 1023) >> 10;
    int base = t * chunk;
    int s = 0;
    for (int k = 0; k < chunk; k++) {
        int i = base + k;
        if (i < N) s += sDeg[i];
    }
    int lane = t & 31, w = t >> 5;
    int pre = s;
#pragma unroll
    for (int o = 1; o < 32; o <<= 1) {
        int u = __shfl_up_sync(0xffffffffu, pre, o);
        if (lane >= o) pre += u;
    }
    if (lane == 31) warpTot[w] = pre;
    __syncthreads();
    if (w == 0) {
        int v = warpTot[lane];
#pragma unroll
        for (int o = 1; o < 32; o <<= 1) {
            int u = __shfl_up_sync(0xffffffffu, v, o);
            if (lane >= o) v += u;
        }
        warpTot[lane] = v;
    }
    __syncthreads();
    int excl = pre - s + (w ? warpTot[w - 1] : 0);
    for (int k = 0; k < chunk; k++) {
        int i = base + k;
        if (i < N) { sOff[i] = excl; excl += sDeg[i]; }
    }
    __syncthreads();
    for (int idx = t; idx < N; idx += 1024) {
        int v = sOff[idx];
        g_off[idx] = v;
        g_cur[idx] = v;
    }
    if (t == 1023) g_off[N] = excl;
}

// ticket scatter: packed edge record at CSR position
__global__ void k_scatter(const int* __restrict__ iv, const int* __restrict__ jv,
                          const float* __restrict__ factor,
                          const float* __restrict__ sph0, const float* __restrict__ sph1,
                          int E) {
    int e = blockIdx.x * blockDim.x + threadIdx.x;
    if (e >= E) return;
    int i = iv[e];
    int pos = atomicAdd(&g_cur[i], 1);
    float4 A, B, C;
    A.x = __int_as_float(jv[e]);
    A.y = __int_as_float(e);
    A.z = __ldg(factor + e);
    A.w = __ldg(sph1 + (size_t)e * 3 + 0);
    B.x = __ldg(sph1 + (size_t)e * 3 + 1);
    B.y = __ldg(sph1 + (size_t)e * 3 + 2);
    B.z = __ldg(sph0 + (size_t)e * 5 + 0);
    B.w = __ldg(sph0 + (size_t)e * 5 + 1);
    C.x = __ldg(sph0 + (size_t)e * 5 + 2);
    C.y = __ldg(sph0 + (size_t)e * 5 + 3);
    C.z = __ldg(sph0 + (size_t)e * 5 + 4);
    C.w = 0.f;
    g_pack[(size_t)pos * 3 + 0] = A;
    g_pack[(size_t)pos * 3 + 1] = B;
    g_pack[(size_t)pos * 3 + 2] = C;
}

// ---------------------------------------------------------------------------
// gather: warp per node, lane owns cols {2*lane, 2*lane+1}
__global__ void __launch_bounds__(256) k_gather(const float* __restrict__ rbf, int N) {
    int w = (blockIdx.x * blockDim.x + threadIdx.x) >> 5;
    if (w >= N) return;
    int lane = threadIdx.x & 31;
    float2 acc[9];
#pragma unroll
    for (int c = 0; c < 9; c++) acc[c] = make_float2(0.f, 0.f);
    int s = g_off[w], eend = g_off[w + 1];
    for (int k = s; k < eend; k++) {
        float4 A = g_pack[(size_t)k * 3 + 0];
        float4 B = g_pack[(size_t)k * 3 + 1];
        float4 C = g_pack[(size_t)k * 3 + 2];
        int j = __float_as_int(A.x);
        int e = __float_as_int(A.y);
        float2 xj = *(const float2*)(g_x + (size_t)j * 64 + lane * 2);
        float2 rb = __ldg((const float2*)(rbf + (size_t)e * 64) + lane);
        float l0x = xj.x * rb.x * A.z;
        float l0y = xj.y * rb.y * A.z;
        acc[0].x += l0x;                      acc[0].y += l0y;
        acc[1].x = fmaf(A.w, l0x, acc[1].x);  acc[1].y = fmaf(A.w, l0y, acc[1].y);
        acc[2].x = fmaf(B.x, l0x, acc[2].x);  acc[2].y = fmaf(B.x, l0y, acc[2].y);
        acc[3].x = fmaf(B.y, l0x, acc[3].x);  acc[3].y = fmaf(B.y, l0y, acc[3].y);
        acc[4].x = fmaf(B.z, l0x, acc[4].x);  acc[4].y = fmaf(B.z, l0y, acc[4].y);
        acc[5].x = fmaf(B.w, l0x, acc[5].x);  acc[5].y = fmaf(B.w, l0y, acc[5].y);
        acc[6].x = fmaf(C.x, l0x, acc[6].x);  acc[6].y = fmaf(C.x, l0y, acc[6].y);
        acc[7].x = fmaf(C.y, l0x, acc[7].x);  acc[7].y = fmaf(C.y, l0y, acc[7].y);
        acc[8].x = fmaf(C.z, l0x, acc[8].x);  acc[8].y = fmaf(C.z, l0y, acc[8].y);
    }
    float* base = g_agg + (size_t)w * 576 + lane * 2;
#pragma unroll
    for (int c = 0; c < 9; c++)
        *(float2*)(base + c * 64) = acc[c];
}

// ---------------------------------------------------------------------------
// k_up_mma: tf32 mma.sync. 64 nodes/block, blockIdx.y = matrix m.
// Per channel: A = (_x*agg_ch)[64 nodes x 64 K], B = W[64 K x 128 out].
// 8 warps 2m x 4n, warp tile 32x32. Square-accumulate across channels (m>0).
#define SV_S 68
#define SU_S 136
__global__ void __launch_bounds__(256) k_up_mma(
    const float* __restrict__ W0, const float* __restrict__ b0,
    const float* __restrict__ W1, const float* __restrict__ Wh, int N) {
    extern __shared__ float sm[];
    float* sV = sm;              // 64*68  = 4352
    float* sW = sm + 4352;       // 64*136 = 8704
    int t = threadIdx.x, lane = t & 31, wid = t >> 5;
    int wm = wid & 1, wn = wid >> 1;
    int qr = lane >> 2, qc = lane & 3;
    int m = blockIdx.y;
    int tile0 = blockIdx.x * 64;

    const float* W = (m == 0) ? W0 : (m == 1) ? W1 : Wh;
    int chBase = (m == 0) ? 0 : (m == 1) ? 1 : 4;
    int nch    = (m == 0) ? 1 : (m == 1) ? 3 : 5;

    // stage W [64 k][128 out], tf32-rounded
    for (int idx = t; idx < 64 * 32; idx += 256) {
        int r = idx >> 5, c4 = (idx & 31) * 4;
        float4 v = tf32r4(__ldg((const float4*)(W + (size_t)r * 128 + c4)));
        *(float4*)(sW + r * SU_S + c4) = v;
    }

    float facc[2][4][4];
#pragma unroll
    for (int mt = 0; mt < 2; mt++)
#pragma unroll
        for (int nt = 0; nt < 4; nt++)
#pragma unroll
            for (int q = 0; q < 4; q++) facc[mt][nt][q] = 0.f;

    for (int ch = 0; ch < nch; ch++) {
        __syncthreads();
        // V tile: 64 nodes x 64 K, v = _x * agg[ch]
        for (int idx = t; idx < 1024; idx += 256) {
            int r = idx >> 4, c4 = (idx & 15) * 4;
            int n = tile0 + r;
            const float4 a  = *(const float4*)(g_agg + (size_t)n * 576 + (chBase + ch) * 64 + c4);
            const float4 xv = *(const float4*)(g_x + (size_t)n * 64 + c4);
            float4 v;
            v.x = tf32r(a.x * xv.x); v.y = tf32r(a.y * xv.y);
            v.z = tf32r(a.z * xv.z); v.w = tf32r(a.w * xv.w);
            *(float4*)(sV + r * SV_S + c4) = v;
        }
        __syncthreads();

        float acc[2][4][4];
#pragma unroll
        for (int mt = 0; mt < 2; mt++)
#pragma unroll
            for (int nt = 0; nt < 4; nt++)
#pragma unroll
                for (int q = 0; q < 4; q++) acc[mt][nt][q] = 0.f;

#pragma unroll
        for (int k8 = 0; k8 < 8; k8++) {
            int kb = k8 * 8;
            uint32_t a[2][4];
#pragma unroll
            for (int mt = 0; mt < 2; mt++) {
                const uint32_t* p = (const uint32_t*)sV +
                    (wm * 32 + mt * 16 + qr) * SV_S + kb + qc;
                a[mt][0] = p[0]; a[mt][2] = p[4];
                a[mt][1] = p[8 * SV_S]; a[mt][3] = p[8 * SV_S + 4];
            }
#pragma unroll
            for (int nt = 0; nt < 4; nt++) {
                const uint32_t* p = (const uint32_t*)sW +
                    (kb + qc) * SU_S + wn * 32 + nt * 8 + qr;
                uint32_t b0v = p[0], b1v = p[4 * SU_S];
                mma_tf32(acc[0][nt], a[0], b0v, b1v);
                mma_tf32(acc[1][nt], a[1], b0v, b1v);
            }
        }
        if (m == 0) {
#pragma unroll
            for (int mt = 0; mt < 2; mt++)
#pragma unroll
                for (int nt = 0; nt < 4; nt++)
#pragma unroll
                    for (int q = 0; q < 4; q++) facc[mt][nt][q] = acc[mt][nt][q];
        } else {
#pragma unroll
            for (int mt = 0; mt < 2; mt++)
#pragma unroll
                for (int nt = 0; nt < 4; nt++)
#pragma unroll
                    for (int q = 0; q < 4; q++)
                        facc[mt][nt][q] = fmaf(acc[mt][nt][q], acc[mt][nt][q], facc[mt][nt][q]);
        }
    }

    // epilogue -> g_node[n][m*128 + col]
#pragma unroll
    for (int mt = 0; mt < 2; mt++) {
#pragma unroll
        for (int half = 0; half < 2; half++) {
            int n = tile0 + wm * 32 + mt * 16 + qr + half * 8;
            if (n < N) {
#pragma unroll
                for (int nt = 0; nt < 4; nt++) {
                    int c = wn * 32 + nt * 8 + qc * 2;
                    float2 o;
                    o.x = facc[mt][nt][half * 2 + 0];
                    o.y = facc[mt][nt][half * 2 + 1];
                    if (m == 0) { o.x += __ldg(b0 + c); o.y += __ldg(b0 + c + 1); }
                    *(float2*)(g_node + (size_t)n * 384 + m * 128 + c) = o;
                }
            }
        }
    }
}

// ---------------------------------------------------------------------------
// k_mlp_mma: tf32 mma.sync. 64 rows/block, 8 warps 2m x 4n, warp tile 32x64.
#define SN_S 388
#define SW_S 264
#define SH_S 388
__global__ void __launch_bounds__(256) k_mlp_mma(
    const float* __restrict__ Wn1, const float* __restrict__ bn1,
    const float* __restrict__ lng, const float* __restrict__ lnb,
    const float* __restrict__ Wn2, const float* __restrict__ bn2,
    const float* __restrict__ x, float* __restrict__ out, int N) {
    extern __shared__ float sm[];
    float* sN = sm;                  // 64*388 = 24832 floats
    float* sW = sm + 24832;          // 64*264 = 16896 floats
    float* sH = sm;                  // alias sN after GEMM1 (stride SH_S=SN_S)
    int t = threadIdx.x, lane = t & 31, wid = t >> 5;
    int wm = wid & 1, wn = wid >> 1;
    int row0 = blockIdx.x * 64;
    int qr = lane >> 2, qc = lane & 3;

    // stage node tile (tf32-rounded)
    for (int idx = t; idx < 64 * 96; idx += 256) {
        int r = idx / 96, c4 = (idx - r * 96) * 4;
        float4 v = tf32r4(*(const float4*)(g_node + (size_t)(row0 + r) * 384 + c4));
        *(float4*)(sN + r * SN_S + c4) = v;
    }

    float acc[2][8][4];
#pragma unroll
    for (int mt = 0; mt < 2; mt++)
#pragma unroll
        for (int nt = 0; nt < 8; nt++)
#pragma unroll
            for (int q = 0; q < 4; q++) acc[mt][nt][q] = 0.f;

    // ---------------- GEMM1: K = 384, 6 chunks of 64
    for (int kc = 0; kc < 6; kc++) {
        __syncthreads();
        for (int idx = t; idx < 64 * 64; idx += 256) {
            int r = idx >> 6, c4 = (idx & 63) * 4;
            float4 v = tf32r4(*(const float4*)(Wn1 + (size_t)(kc * 64 + r) * 256 + c4));
            *(float4*)(sW + r * SW_S + c4) = v;
        }
        __syncthreads();
#pragma unroll
        for (int k8 = 0; k8 < 8; k8++) {
            int kb = kc * 64 + k8 * 8;
            uint32_t a[2][4];
#pragma unroll
            for (int mt = 0; mt < 2; mt++) {
                const uint32_t* p = (const uint32_t*)sN +
                    (wm * 32 + mt * 16 + qr) * SN_S + kb + qc;
                a[mt][0] = p[0]; a[mt][2] = p[4];
                a[mt][1] = p[8 * SN_S]; a[mt][3] = p[8 * SN_S + 4];
            }
#pragma unroll
            for (int nt = 0; nt < 8; nt++) {
                const uint32_t* p = (const uint32_t*)sW +
                    (k8 * 8 + qc) * SW_S + wn * 64 + nt * 8 + qr;
                uint32_t b0 = p[0], b1 = p[4 * SW_S];
                mma_tf32(acc[0][nt], a[0], b0, b1);
                mma_tf32(acc[1][nt], a[1], b0, b1);
            }
        }
    }
    __syncthreads();

    // spill C1 to sH (alias of sN)
#pragma unroll
    for (int mt = 0; mt < 2; mt++)
#pragma unroll
        for (int nt = 0; nt < 8; nt++) {
            int r = wm * 32 + mt * 16 + qr;
            int c = wn * 64 + nt * 8 + qc * 2;
            *(float2*)(sH + r * SH_S + c) = make_float2(acc[mt][nt][0], acc[mt][nt][1]);
            *(float2*)(sH + (r + 8) * SH_S + c) = make_float2(acc[mt][nt][2], acc[mt][nt][3]);
        }
    __syncthreads();

    // LN + SiLU per row (warp per row, 8 rows/warp), tf32-round in place
#pragma unroll
    for (int rr = 0; rr < 8; rr++) {
        int r = wid * 8 + rr;
        float* hr = sH + r * SH_S;
        float vv[8];
        float s1 = 0.f, s2 = 0.f;
#pragma unroll
        for (int k2 = 0; k2 < 8; k2++) {
            int col = lane + 32 * k2;
            float v = hr[col] + __ldg(bn1 + col);
            vv[k2] = v; s1 += v; s2 = fmaf(v, v, s2);
        }
#pragma unroll
        for (int o = 16; o > 0; o >>= 1) {
            s1 += __shfl_xor_sync(0xffffffffu, s1, o);
            s2 += __shfl_xor_sync(0xffffffffu, s2, o);
        }
        float mean = s1 * (1.f / 256.f);
        float var = s2 * (1.f / 256.f) - mean * mean;
        float rstd = rsqrtf(var + 1e-5f);
#pragma unroll
        for (int k2 = 0; k2 < 8; k2++) {
            int col = lane + 32 * k2;
            float y = (vv[k2] - mean) * rstd * __ldg(lng + col) + __ldg(lnb + col);
            hr[col] = tf32r(y / (1.f + __expf(-y)));
        }
    }
    __syncthreads();

    // ---------------- GEMM2: K = 256, 4 chunks of 64
#pragma unroll
    for (int mt = 0; mt < 2; mt++)
#pragma unroll
        for (int nt = 0; nt < 8; nt++)
#pragma unroll
            for (int q = 0; q < 4; q++) acc[mt][nt][q] = 0.f;

    for (int kc = 0; kc < 4; kc++) {
        __syncthreads();
        for (int idx = t; idx < 64 * 64; idx += 256) {
            int r = idx >> 6, c4 = (idx & 63) * 4;
            float4 v = tf32r4(*(const float4*)(Wn2 + (size_t)(kc * 64 + r) * 256 + c4));
            *(float4*)(sW + r * SW_S + c4) = v;
        }
        __syncthreads();
#pragma unroll
        for (int k8 = 0; k8 < 8; k8++) {
            int kb = kc * 64 + k8 * 8;
            uint32_t a[2][4];
#pragma unroll
            for (int mt = 0; mt < 2; mt++) {
                const uint32_t* p = (const uint32_t*)sH +
                    (wm * 32 + mt * 16 + qr) * SH_S + kb + qc;
                a[mt][0] = p[0]; a[mt][2] = p[4];
                a[mt][1] = p[8 * SH_S]; a[mt][3] = p[8 * SH_S + 4];
            }
#pragma unroll
            for (int nt = 0; nt < 8; nt++) {
                const uint32_t* p = (const uint32_t*)sW +
                    (k8 * 8 + qc) * SW_S + wn * 64 + nt * 8 + qr;
                uint32_t b0 = p[0], b1 = p[4 * SW_S];
                mma_tf32(acc[0][nt], a[0], b0, b1);
                mma_tf32(acc[1][nt], a[1], b0, b1);
            }
        }
    }

    // epilogue: + bn2 + x -> out
#pragma unroll
    for (int mt = 0; mt < 2; mt++) {
        int rl = wm * 32 + mt * 16 + qr;
#pragma unroll
        for (int half = 0; half < 2; half++) {
            int rg = row0 + rl + half * 8;
            if (rg < N) {
#pragma unroll
                for (int nt = 0; nt < 8; nt++) {
                    int c = wn * 64 + nt * 8 + qc * 2;
                    float2 xv = __ldg((const float2*)(x + (size_t)rg * 256 + c));
                    float2 o;
                    o.x = acc[mt][nt][half * 2 + 0] + __ldg(bn2 + c) + xv.x;
                    o.y = acc[mt][nt][half * 2 + 1] + __ldg(bn2 + c + 1) + xv.y;
                    *(float2*)(out + (size_t)rg * 256 + c) = o;
                }
            }
        }
    }
}

// ---------------------------------------------------------------------------
extern "C" void kernel_launch(void* const* d_in, const int* in_sizes, int n_in,
                              void* d_out, int out_size) {
    const float* x      = (const float*)d_in[0];
    const float* rbf    = (const float*)d_in[1];
    const float* factor = (const float*)d_in[2];
    const float* sph0   = (const float*)d_in[3];
    const float* sph1   = (const float*)d_in[4];
    const float* Wd     = (const float*)d_in[5];
    const float* bd     = (const float*)d_in[6];
    const float* Wu0    = (const float*)d_in[7];
    const float* bu0    = (const float*)d_in[8];
    const float* Wu1    = (const float*)d_in[9];
    const float* Wuh    = (const float*)d_in[10];
    const float* Wn1    = (const float*)d_in[11];
    const float* bn1    = (const float*)d_in[12];
    const float* lng    = (const float*)d_in[13];
    const float* lnb    = (const float*)d_in[14];
    const float* Wn2    = (const float*)d_in[15];
    const float* bn2    = (const float*)d_in[16];
    const int*   jv     = (const int*)d_in[17];
    const int*   iv     = (const int*)d_in[18];
    float* out = (float*)d_out;

    int N = in_sizes[0] / 256;
    int E = in_sizes[17];

    int mlpSmem = (24832 + 16896) * 4;   // 166,912 B
    int upSmem  = (4352 + 8704) * 4;     // 52,224 B
    cudaFuncSetAttribute(k_up_mma,  cudaFuncAttributeMaxDynamicSharedMemorySize, upSmem);
    cudaFuncSetAttribute(k_scan,    cudaFuncAttributeMaxDynamicSharedMemorySize, 2 * (N + 4) * 4);
    cudaFuncSetAttribute(k_mlp_mma, cudaFuncAttributeMaxDynamicSharedMemorySize, mlpSmem);

    k_down<<<(N + 15) / 16, 256>>>(x, Wd, bd, N);
    k_zero_deg<<<(N + 255) / 256, 256>>>(N);
    k_hist<<<(E + 255) / 256, 256>>>(iv, E);
    k_scan<<<1, 1024, 2 * (N + 4) * 4>>>(N);
    k_scatter<<<(E + 255) / 256, 256>>>(iv, jv, factor, sph0, sph1, E);
    k_gather<<<(N + 7) / 8, 256>>>(rbf, N);
    dim3 upGrid((N + 63) / 64, 3);
    k_up_mma<<<upGrid, 256, upSmem>>>(Wu0, bu0, Wu1, Wuh, N);
    k_mlp_mma<<<(N + 63) / 64, 256, mlpSmem>>>(Wn1, bn1, lng, lnb, Wn2, bn2, x, out, N);
}

// round 7
// speedup vs baseline: 3.6013x; 1.1549x over previous
#include <cuda_runtime.h>
#include <cstdint>

// SphConv3 fused pipeline v6.1: tf32 mma + cp.async double-buffered staging.
// (v6 with the k_up_mma staging index bugs fixed.)

#define N_MAX 26001
#define E_MAX 520001

__device__ float  g_x[(size_t)N_MAX * 64];
__device__ float  g_agg[(size_t)N_MAX * 576];    // holds V = tf32(x*agg)
__device__ float  g_node[(size_t)N_MAX * 384];   // tf32-rounded
__device__ float4 g_pack[(size_t)E_MAX * 3];
__device__ int    g_deg[N_MAX];
__device__ int    g_off[N_MAX + 1];
__device__ int    g_cur[N_MAX];
__device__ float  g_wn1r[384 * 256];
__device__ float  g_wn2r[256 * 256];
__device__ float  g_wur[3 * 64 * 128];

static __device__ __forceinline__ float4 f4fma(float s, float4 w, float4 acc) {
    acc.x = fmaf(s, w.x, acc.x); acc.y = fmaf(s, w.y, acc.y);
    acc.z = fmaf(s, w.z, acc.z); acc.w = fmaf(s, w.w, acc.w);
    return acc;
}
static __device__ __forceinline__ float tf32r(float x) {
    float r;
    asm("cvt.rna.tf32.f32 %0, %1;" : "=f"(r) : "f"(x));
    return r;
}
static __device__ __forceinline__ float4 tf32r4(float4 v) {
    v.x = tf32r(v.x); v.y = tf32r(v.y); v.z = tf32r(v.z); v.w = tf32r(v.w);
    return v;
}
static __device__ __forceinline__ void mma_tf32(float* c, const uint32_t* a,
                                                uint32_t b0, uint32_t b1) {
    asm volatile(
        "mma.sync.aligned.m16n8k8.row.col.f32.tf32.tf32.f32 "
        "{%0,%1,%2,%3}, {%4,%5,%6,%7}, {%8,%9}, {%0,%1,%2,%3};"
        : "+f"(c[0]), "+f"(c[1]), "+f"(c[2]), "+f"(c[3])
        : "r"(a[0]), "r"(a[1]), "r"(a[2]), "r"(a[3]), "r"(b0), "r"(b1));
}
static __device__ __forceinline__ void cp16(float* s, const float* g) {
    uint32_t sa = (uint32_t)__cvta_generic_to_shared(s);
    asm volatile("cp.async.ca.shared.global [%0], [%1], 16;" :: "r"(sa), "l"(g));
}
#define CP_COMMIT() asm volatile("cp.async.commit_group;" ::: "memory")
#define CP_WAIT0()  asm volatile("cp.async.wait_group 0;" ::: "memory")
#define CP_WAIT1()  asm volatile("cp.async.wait_group 1;" ::: "memory")

// ---------------------------------------------------------------------------
__global__ void k_prep(const float* __restrict__ Wn1, const float* __restrict__ Wn2,
                       const float* __restrict__ W0, const float* __restrict__ W1,
                       const float* __restrict__ Wh) {
    int i = blockIdx.x * 256 + threadIdx.x;
    if (i < 24576)      ((float4*)g_wn1r)[i] = tf32r4(__ldg((const float4*)Wn1 + i));
    else if (i < 40960) ((float4*)g_wn2r)[i - 24576] = tf32r4(__ldg((const float4*)Wn2 + (i - 24576)));
    else if (i < 43008) ((float4*)g_wur)[i - 40960] = tf32r4(__ldg((const float4*)W0 + (i - 40960)));
    else if (i < 45056) ((float4*)g_wur)[i - 40960] = tf32r4(__ldg((const float4*)W1 + (i - 43008)));
    else if (i < 47104) ((float4*)g_wur)[i - 40960] = tf32r4(__ldg((const float4*)Wh + (i - 45056)));
}

__global__ void k_zero_deg(int N) {
    int i = blockIdx.x * blockDim.x + threadIdx.x;
    if (i < N) g_deg[i] = 0;
}

// ---------------------------------------------------------------------------
// _x = x @ W_down + b_down.  16 rows/block, 256 thr.
__global__ void k_down(const float* __restrict__ x, const float* __restrict__ Wd,
                       const float* __restrict__ bd, int N) {
    __shared__ float sX[16 * 256];
    int t = threadIdx.x;
    int row0 = blockIdx.x * 16;
    const float4* x4 = (const float4*)x + (size_t)row0 * 64;
    int lim = (N - row0) * 64;
    for (int idx = t; idx < 1024; idx += 256)
        ((float4*)sX)[idx] = (idx < lim) ? x4[idx] : make_float4(0.f, 0.f, 0.f, 0.f);
    __syncthreads();
    int cg = t & 15, rl = t >> 4;
    int row = row0 + rl;
    if (row >= N) return;
    float4 acc = *(const float4*)(bd + cg * 4);
    const float* xr = sX + rl * 256;
#pragma unroll 8
    for (int k = 0; k < 256; k++) {
        float4 w = __ldg((const float4*)(Wd + k * 64) + cg);
        acc = f4fma(xr[k], w, acc);
    }
    *(float4*)(g_x + (size_t)row * 64 + cg * 4) = acc;
}

// ---------------------------------------------------------------------------
__global__ void k_hist(const int* __restrict__ iv, int E) {
    int e = blockIdx.x * blockDim.x + threadIdx.x;
    if (e < E) atomicAdd(&g_deg[iv[e]], 1);
}

// single-block scan, smem-staged
__global__ void k_scan(int N) {
    extern __shared__ int si[];
    int* sDeg = si;
    int* sOff = si + N;
    __shared__ int warpTot[32];
    int t = threadIdx.x;
    for (int idx = t; idx < N; idx += 1024) sDeg[idx] = g_deg[idx];
    __syncthreads();
    int chunk = (N + 1023) >> 10;
    int base = t * chunk;
    int s = 0;
    for (int k = 0; k < chunk; k++) {
        int i = base + k;
        if (i < N) s += sDeg[i];
    }
    int lane = t & 31, w = t >> 5;
    int pre = s;
#pragma unroll
    for (int o = 1; o < 32; o <<= 1) {
        int u = __shfl_up_sync(0xffffffffu, pre, o);
        if (lane >= o) pre += u;
    }
    if (lane == 31) warpTot[w] = pre;
    __syncthreads();
    if (w == 0) {
        int v = warpTot[lane];
#pragma unroll
        for (int o = 1; o < 32; o <<= 1) {
            int u = __shfl_up_sync(0xffffffffu, v, o);
            if (lane >= o) v += u;
        }
        warpTot[lane] = v;
    }
    __syncthreads();
    int excl = pre - s + (w ? warpTot[w - 1] : 0);
    for (int k = 0; k < chunk; k++) {
        int i = base + k;
        if (i < N) { sOff[i] = excl; excl += sDeg[i]; }
    }
    __syncthreads();
    for (int idx = t; idx < N; idx += 1024) {
        int v = sOff[idx];
        g_off[idx] = v;
        g_cur[idx] = v;
    }
    if (t == 1023) g_off[N] = excl;
}

// ticket scatter: packed edge record at CSR position
__global__ void k_scatter(const int* __restrict__ iv, const int* __restrict__ jv,
                          const float* __restrict__ factor,
                          const float* __restrict__ sph0, const float* __restrict__ sph1,
                          int E) {
    int e = blockIdx.x * blockDim.x + threadIdx.x;
    if (e >= E) return;
    int i = iv[e];
    int pos = atomicAdd(&g_cur[i], 1);
    float4 A, B, C;
    A.x = __int_as_float(jv[e]);
    A.y = __int_as_float(e);
    A.z = __ldg(factor + e);
    A.w = __ldg(sph1 + (size_t)e * 3 + 0);
    B.x = __ldg(sph1 + (size_t)e * 3 + 1);
    B.y = __ldg(sph1 + (size_t)e * 3 + 2);
    B.z = __ldg(sph0 + (size_t)e * 5 + 0);
    B.w = __ldg(sph0 + (size_t)e * 5 + 1);
    C.x = __ldg(sph0 + (size_t)e * 5 + 2);
    C.y = __ldg(sph0 + (size_t)e * 5 + 3);
    C.z = __ldg(sph0 + (size_t)e * 5 + 4);
    C.w = 0.f;
    g_pack[(size_t)pos * 3 + 0] = A;
    g_pack[(size_t)pos * 3 + 1] = B;
    g_pack[(size_t)pos * 3 + 2] = C;
}

// ---------------------------------------------------------------------------
// gather: warp per node; writes V = tf32(_x * agg) per channel
__global__ void __launch_bounds__(256) k_gather(const float* __restrict__ rbf, int N) {
    int w = (blockIdx.x * blockDim.x + threadIdx.x) >> 5;
    if (w >= N) return;
    int lane = threadIdx.x & 31;
    float2 acc[9];
#pragma unroll
    for (int c = 0; c < 9; c++) acc[c] = make_float2(0.f, 0.f);
    int s = g_off[w], eend = g_off[w + 1];
    for (int k = s; k < eend; k++) {
        float4 A = g_pack[(size_t)k * 3 + 0];
        float4 B = g_pack[(size_t)k * 3 + 1];
        float4 C = g_pack[(size_t)k * 3 + 2];
        int j = __float_as_int(A.x);
        int e = __float_as_int(A.y);
        float2 xj = *(const float2*)(g_x + (size_t)j * 64 + lane * 2);
        float2 rb = __ldg((const float2*)(rbf + (size_t)e * 64) + lane);
        float l0x = xj.x * rb.x * A.z;
        float l0y = xj.y * rb.y * A.z;
        acc[0].x += l0x;                      acc[0].y += l0y;
        acc[1].x = fmaf(A.w, l0x, acc[1].x);  acc[1].y = fmaf(A.w, l0y, acc[1].y);
        acc[2].x = fmaf(B.x, l0x, acc[2].x);  acc[2].y = fmaf(B.x, l0y, acc[2].y);
        acc[3].x = fmaf(B.y, l0x, acc[3].x);  acc[3].y = fmaf(B.y, l0y, acc[3].y);
        acc[4].x = fmaf(B.z, l0x, acc[4].x);  acc[4].y = fmaf(B.z, l0y, acc[4].y);
        acc[5].x = fmaf(B.w, l0x, acc[5].x);  acc[5].y = fmaf(B.w, l0y, acc[5].y);
        acc[6].x = fmaf(C.x, l0x, acc[6].x);  acc[6].y = fmaf(C.x, l0y, acc[6].y);
        acc[7].x = fmaf(C.y, l0x, acc[7].x);  acc[7].y = fmaf(C.y, l0y, acc[7].y);
        acc[8].x = fmaf(C.z, l0x, acc[8].x);  acc[8].y = fmaf(C.z, l0y, acc[8].y);
    }
    float2 xv = *(const float2*)(g_x + (size_t)w * 64 + lane * 2);
    float* base = g_agg + (size_t)w * 576 + lane * 2;
#pragma unroll
    for (int c = 0; c < 9; c++) {
        float2 v;
        v.x = tf32r(acc[c].x * xv.x);
        v.y = tf32r(acc[c].y * xv.y);
        *(float2*)(base + c * 64) = v;
    }
}

// ---------------------------------------------------------------------------
// k_up_mma: tf32 mma. 64 nodes/block, blockIdx.y = matrix m.
// V tiles double-buffered via cp.async; W staged once via cp.async.
#define SV_S 68
#define SU_S 136
__global__ void __launch_bounds__(256) k_up_mma(const float* __restrict__ b0, int N) {
    extern __shared__ float sm[];
    float* sW = sm;               // 64*136 = 8704
    float* sV[2] = { sm + 8704, sm + 8704 + 4352 };
    int t = threadIdx.x, lane = t & 31, wid = t >> 5;
    int wm = wid & 1, wn = wid >> 1;
    int qr = lane >> 2, qc = lane & 3;
    int m = blockIdx.y;
    int tile0 = blockIdx.x * 64;

    int chBase = (m == 0) ? 0 : (m == 1) ? 1 : 4;
    int nch    = (m == 0) ? 1 : (m == 1) ? 3 : 5;

    // stage W [64 rows x 128 cols] = 2048 f4: r = idx>>5 (32 f4/row)
    {
        const float* Wg = g_wur + m * 8192;
#pragma unroll
        for (int i = 0; i < 8; i++) {
            int idx = t + i * 256;
            int r = idx >> 5, c4 = (idx & 31) * 4;
            cp16(sW + r * SU_S + c4, Wg + r * 128 + c4);
        }
        // V channel 0: 64 rows x 16 f4 = 1024 f4, 4 per thread
#pragma unroll
        for (int i = 0; i < 4; i++) {
            int idx = t + i * 256;
            int r = idx >> 4, c4 = (idx & 15) * 4;
            cp16(sV[0] + r * SV_S + c4,
                 g_agg + (size_t)(tile0 + r) * 576 + chBase * 64 + c4);
        }
        CP_COMMIT();
    }

    float facc[2][4][4];
#pragma unroll
    for (int mt = 0; mt < 2; mt++)
#pragma unroll
        for (int nt = 0; nt < 4; nt++)
#pragma unroll
            for (int q = 0; q < 4; q++) facc[mt][nt][q] = 0.f;

    for (int ch = 0; ch < nch; ch++) {
        if (ch + 1 < nch) {
#pragma unroll
            for (int i = 0; i < 4; i++) {
                int idx = t + i * 256;
                int r = idx >> 4, c4 = (idx & 15) * 4;
                cp16(sV[(ch + 1) & 1] + r * SV_S + c4,
                     g_agg + (size_t)(tile0 + r) * 576 + (chBase + ch + 1) * 64 + c4);
            }
            CP_COMMIT();
            CP_WAIT1();
        } else {
            CP_WAIT0();
        }
        __syncthreads();
        const float* V = sV[ch & 1];

        float acc[2][4][4];
#pragma unroll
        for (int mt = 0; mt < 2; mt++)
#pragma unroll
            for (int nt = 0; nt < 4; nt++)
#pragma unroll
                for (int q = 0; q < 4; q++) acc[mt][nt][q] = 0.f;

#pragma unroll
        for (int k8 = 0; k8 < 8; k8++) {
            int kb = k8 * 8;
            uint32_t a[2][4];
#pragma unroll
            for (int mt = 0; mt < 2; mt++) {
                const uint32_t* p = (const uint32_t*)V +
                    (wm * 32 + mt * 16 + qr) * SV_S + kb + qc;
                a[mt][0] = p[0]; a[mt][2] = p[4];
                a[mt][1] = p[8 * SV_S]; a[mt][3] = p[8 * SV_S + 4];
            }
#pragma unroll
            for (int nt = 0; nt < 4; nt++) {
                const uint32_t* p = (const uint32_t*)sW +
                    (kb + qc) * SU_S + wn * 32 + nt * 8 + qr;
                uint32_t b0v = p[0], b1v = p[4 * SU_S];
                mma_tf32(acc[0][nt], a[0], b0v, b1v);
                mma_tf32(acc[1][nt], a[1], b0v, b1v);
            }
        }
        if (m == 0) {
#pragma unroll
            for (int mt = 0; mt < 2; mt++)
#pragma unroll
                for (int nt = 0; nt < 4; nt++)
#pragma unroll
                    for (int q = 0; q < 4; q++) facc[mt][nt][q] = acc[mt][nt][q];
        } else {
#pragma unroll
            for (int mt = 0; mt < 2; mt++)
#pragma unroll
                for (int nt = 0; nt < 4; nt++)
#pragma unroll
                    for (int q = 0; q < 4; q++)
                        facc[mt][nt][q] = fmaf(acc[mt][nt][q], acc[mt][nt][q], facc[mt][nt][q]);
        }
        __syncthreads();
    }

    // epilogue -> g_node (tf32-rounded)
#pragma unroll
    for (int mt = 0; mt < 2; mt++) {
#pragma unroll
        for (int half = 0; half < 2; half++) {
            int n = tile0 + wm * 32 + mt * 16 + qr + half * 8;
            if (n < N) {
#pragma unroll
                for (int nt = 0; nt < 4; nt++) {
                    int c = wn * 32 + nt * 8 + qc * 2;
                    float2 o;
                    o.x = facc[mt][nt][half * 2 + 0];
                    o.y = facc[mt][nt][half * 2 + 1];
                    if (m == 0) { o.x += __ldg(b0 + c); o.y += __ldg(b0 + c + 1); }
                    o.x = tf32r(o.x); o.y = tf32r(o.y);
                    *(float2*)(g_node + (size_t)n * 384 + m * 128 + c) = o;
                }
            }
        }
    }
}

// ---------------------------------------------------------------------------
// k_mlp_mma: tf32 mma. 64 rows/block, 8 warps 2m x 4n, warp tile 32x64.
// Weights cp.async double-buffered in K=32 chunks.
#define SN_S 388
#define SW_S 264
__global__ void __launch_bounds__(256) k_mlp_mma(
    const float* __restrict__ bn1, const float* __restrict__ lng,
    const float* __restrict__ lnb, const float* __restrict__ bn2,
    const float* __restrict__ x, float* __restrict__ out, int N) {
    extern __shared__ float sm[];
    float* sN = sm;                         // 64*388 = 24832
    float* sWb[2] = { sm + 24832, sm + 24832 + 8448 };  // each 32*264 = 8448
    float* sH = sm;                         // alias sN
    int t = threadIdx.x, lane = t & 31, wid = t >> 5;
    int wm = wid & 1, wn = wid >> 1;
    int row0 = blockIdx.x * 64;
    int qr = lane >> 2, qc = lane & 3;

    // stage node tile via cp.async (24 f4/thread) + W1 chunk 0 (8 f4/thread)
    {
#pragma unroll
        for (int i = 0; i < 24; i++) {
            int idx = t + i * 256;
            int r = idx / 96, c4 = (idx - r * 96) * 4;
            cp16(sN + r * SN_S + c4, g_node + (size_t)(row0 + r) * 384 + c4);
        }
#pragma unroll
        for (int i = 0; i < 8; i++) {
            int idx = t + i * 256;
            int r = idx >> 6, c4 = (idx & 63) * 4;
            cp16(sWb[0] + r * SW_S + c4, g_wn1r + (size_t)r * 256 + c4);
        }
        CP_COMMIT();
    }

    float acc[2][8][4];
#pragma unroll
    for (int mt = 0; mt < 2; mt++)
#pragma unroll
        for (int nt = 0; nt < 8; nt++)
#pragma unroll
            for (int q = 0; q < 4; q++) acc[mt][nt][q] = 0.f;

    // ---------------- GEMM1: K = 384, 12 chunks of 32
    for (int kc = 0; kc < 12; kc++) {
        if (kc + 1 < 12) {
#pragma unroll
            for (int i = 0; i < 8; i++) {
                int idx = t + i * 256;
                int r = idx >> 6, c4 = (idx & 63) * 4;
                cp16(sWb[(kc + 1) & 1] + r * SW_S + c4,
                     g_wn1r + (size_t)((kc + 1) * 32 + r) * 256 + c4);
            }
            CP_COMMIT();
            CP_WAIT1();
        } else {
            CP_WAIT0();
        }
        __syncthreads();
        const float* sW = sWb[kc & 1];
#pragma unroll
        for (int k8 = 0; k8 < 4; k8++) {
            int kb = kc * 32 + k8 * 8;
            uint32_t a[2][4];
#pragma unroll
            for (int mt = 0; mt < 2; mt++) {
                const uint32_t* p = (const uint32_t*)sN +
                    (wm * 32 + mt * 16 + qr) * SN_S + kb + qc;
                a[mt][0] = p[0]; a[mt][2] = p[4];
                a[mt][1] = p[8 * SN_S]; a[mt][3] = p[8 * SN_S + 4];
            }
#pragma unroll
            for (int nt = 0; nt < 8; nt++) {
                const uint32_t* p = (const uint32_t*)sW +
                    (k8 * 8 + qc) * SW_S + wn * 64 + nt * 8 + qr;
                uint32_t b0 = p[0], b1 = p[4 * SW_S];
                mma_tf32(acc[0][nt], a[0], b0, b1);
                mma_tf32(acc[1][nt], a[1], b0, b1);
            }
        }
        __syncthreads();
    }

    // spill C1 to sH (alias of sN)
#pragma unroll
    for (int mt = 0; mt < 2; mt++)
#pragma unroll
        for (int nt = 0; nt < 8; nt++) {
            int r = wm * 32 + mt * 16 + qr;
            int c = wn * 64 + nt * 8 + qc * 2;
            *(float2*)(sH + r * SN_S + c) = make_float2(acc[mt][nt][0], acc[mt][nt][1]);
            *(float2*)(sH + (r + 8) * SN_S + c) = make_float2(acc[mt][nt][2], acc[mt][nt][3]);
        }
    __syncthreads();

    // LN + SiLU per row (warp per row, 8 rows/warp), tf32-round in place
#pragma unroll
    for (int rr = 0; rr < 8; rr++) {
        int r = wid * 8 + rr;
        float* hr = sH + r * SN_S;
        float vv[8];
        float s1 = 0.f, s2 = 0.f;
#pragma unroll
        for (int k2 = 0; k2 < 8; k2++) {
            int col = lane + 32 * k2;
            float v = hr[col] + __ldg(bn1 + col);
            vv[k2] = v; s1 += v; s2 = fmaf(v, v, s2);
        }
#pragma unroll
        for (int o = 16; o > 0; o >>= 1) {
            s1 += __shfl_xor_sync(0xffffffffu, s1, o);
            s2 += __shfl_xor_sync(0xffffffffu, s2, o);
        }
        float mean = s1 * (1.f / 256.f);
        float var = s2 * (1.f / 256.f) - mean * mean;
        float rstd = rsqrtf(var + 1e-5f);
#pragma unroll
        for (int k2 = 0; k2 < 8; k2++) {
            int col = lane + 32 * k2;
            float y = (vv[k2] - mean) * rstd * __ldg(lng + col) + __ldg(lnb + col);
            hr[col] = tf32r(y / (1.f + __expf(-y)));
        }
    }
    __syncthreads();

    // preload W2 chunk 0
    {
#pragma unroll
        for (int i = 0; i < 8; i++) {
            int idx = t + i * 256;
            int r = idx >> 6, c4 = (idx & 63) * 4;
            cp16(sWb[0] + r * SW_S + c4, g_wn2r + (size_t)r * 256 + c4);
        }
        CP_COMMIT();
    }

    // ---------------- GEMM2: K = 256, 8 chunks of 32
#pragma unroll
    for (int mt = 0; mt < 2; mt++)
#pragma unroll
        for (int nt = 0; nt < 8; nt++)
#pragma unroll
            for (int q = 0; q < 4; q++) acc[mt][nt][q] = 0.f;

    for (int kc = 0; kc < 8; kc++) {
        if (kc + 1 < 8) {
#pragma unroll
            for (int i = 0; i < 8; i++) {
                int idx = t + i * 256;
                int r = idx >> 6, c4 = (idx & 63) * 4;
                cp16(sWb[(kc + 1) & 1] + r * SW_S + c4,
                     g_wn2r + (size_t)((kc + 1) * 32 + r) * 256 + c4);
            }
            CP_COMMIT();
            CP_WAIT1();
        } else {
            CP_WAIT0();
        }
        __syncthreads();
        const float* sW = sWb[kc & 1];
#pragma unroll
        for (int k8 = 0; k8 < 4; k8++) {
            int kb = kc * 32 + k8 * 8;
            uint32_t a[2][4];
#pragma unroll
            for (int mt = 0; mt < 2; mt++) {
                const uint32_t* p = (const uint32_t*)sH +
                    (wm * 32 + mt * 16 + qr) * SN_S + kb + qc;
                a[mt][0] = p[0]; a[mt][2] = p[4];
                a[mt][1] = p[8 * SN_S]; a[mt][3] = p[8 * SN_S + 4];
            }
#pragma unroll
            for (int nt = 0; nt < 8; nt++) {
                const uint32_t* p = (const uint32_t*)sW +
                    (k8 * 8 + qc) * SW_S + wn * 64 + nt * 8 + qr;
                uint32_t b0 = p[0], b1 = p[4 * SW_S];
                mma_tf32(acc[0][nt], a[0], b0, b1);
                mma_tf32(acc[1][nt], a[1], b0, b1);
            }
        }
        __syncthreads();
    }

    // epilogue: + bn2 + x -> out
#pragma unroll
    for (int mt = 0; mt < 2; mt++) {
        int rl = wm * 32 + mt * 16 + qr;
#pragma unroll
        for (int half = 0; half < 2; half++) {
            int rg = row0 + rl + half * 8;
            if (rg < N) {
#pragma unroll
                for (int nt = 0; nt < 8; nt++) {
                    int c = wn * 64 + nt * 8 + qc * 2;
                    float2 xv = __ldg((const float2*)(x + (size_t)rg * 256 + c));
                    float2 o;
                    o.x = acc[mt][nt][half * 2 + 0] + __ldg(bn2 + c) + xv.x;
                    o.y = acc[mt][nt][half * 2 + 1] + __ldg(bn2 + c + 1) + xv.y;
                    *(float2*)(out + (size_t)rg * 256 + c) = o;
                }
            }
        }
    }
}

// ---------------------------------------------------------------------------
extern "C" void kernel_launch(void* const* d_in, const int* in_sizes, int n_in,
                              void* d_out, int out_size) {
    const float* x      = (const float*)d_in[0];
    const float* rbf    = (const float*)d_in[1];
    const float* factor = (const float*)d_in[2];
    const float* sph0   = (const float*)d_in[3];
    const float* sph1   = (const float*)d_in[4];
    const float* Wd     = (const float*)d_in[5];
    const float* bd     = (const float*)d_in[6];
    const float* Wu0    = (const float*)d_in[7];
    const float* bu0    = (const float*)d_in[8];
    const float* Wu1    = (const float*)d_in[9];
    const float* Wuh    = (const float*)d_in[10];
    const float* Wn1    = (const float*)d_in[11];
    const float* bn1    = (const float*)d_in[12];
    const float* lng    = (const float*)d_in[13];
    const float* lnb    = (const float*)d_in[14];
    const float* Wn2    = (const float*)d_in[15];
    const float* bn2    = (const float*)d_in[16];
    const int*   jv     = (const int*)d_in[17];
    const int*   iv     = (const int*)d_in[18];
    float* out = (float*)d_out;

    int N = in_sizes[0] / 256;
    int E = in_sizes[17];

    int mlpSmem = (24832 + 2 * 8448) * 4;   // 167,680 B
    int upSmem  = (8704 + 2 * 4352) * 4;    // 69,632 B
    cudaFuncSetAttribute(k_up_mma,  cudaFuncAttributeMaxDynamicSharedMemorySize, upSmem);
    cudaFuncSetAttribute(k_scan,    cudaFuncAttributeMaxDynamicSharedMemorySize, 2 * (N + 4) * 4);
    cudaFuncSetAttribute(k_mlp_mma, cudaFuncAttributeMaxDynamicSharedMemorySize, mlpSmem);

    k_prep<<<184, 256>>>(Wn1, Wn2, Wu0, Wu1, Wuh);
    k_down<<<(N + 15) / 16, 256>>>(x, Wd, bd, N);
    k_zero_deg<<<(N + 255) / 256, 256>>>(N);
    k_hist<<<(E + 255) / 256, 256>>>(iv, E);
    k_scan<<<1, 1024, 2 * (N + 4) * 4>>>(N);
    k_scatter<<<(E + 255) / 256, 256>>>(iv, jv, factor, sph0, sph1, E);
    k_gather<<<(N + 7) / 8, 256>>>(rbf, N);
    dim3 upGrid((N + 63) / 64, 3);
    k_up_mma<<<upGrid, 256, upSmem>>>(bu0, N);
    k_mlp_mma<<<(N + 63) / 64, 256, mlpSmem>>>(bn1, lng, lnb, bn2, x, out, N);
}

// round 8
// speedup vs baseline: 3.7476x; 1.0406x over previous
#include <cuda_runtime.h>
#include <cstdint>

// SphConv3 fused pipeline v7: v6.1 + software-pipelined gather + merged prep.

#define N_MAX 26001
#define E_MAX 520001

__device__ float  g_x[(size_t)N_MAX * 64];
__device__ float  g_agg[(size_t)N_MAX * 576];    // holds V = tf32(x*agg)
__device__ float  g_node[(size_t)N_MAX * 384];   // tf32-rounded
__device__ float4 g_pack[(size_t)E_MAX * 3];
__device__ int    g_deg[N_MAX];
__device__ int    g_off[N_MAX + 1];
__device__ int    g_cur[N_MAX];
__device__ float  g_wn1r[384 * 256];
__device__ float  g_wn2r[256 * 256];
__device__ float  g_wur[3 * 64 * 128];

static __device__ __forceinline__ float4 f4fma(float s, float4 w, float4 acc) {
    acc.x = fmaf(s, w.x, acc.x); acc.y = fmaf(s, w.y, acc.y);
    acc.z = fmaf(s, w.z, acc.z); acc.w = fmaf(s, w.w, acc.w);
    return acc;
}
static __device__ __forceinline__ float tf32r(float x) {
    float r;
    asm("cvt.rna.tf32.f32 %0, %1;" : "=f"(r) : "f"(x));
    return r;
}
static __device__ __forceinline__ float4 tf32r4(float4 v) {
    v.x = tf32r(v.x); v.y = tf32r(v.y); v.z = tf32r(v.z); v.w = tf32r(v.w);
    return v;
}
static __device__ __forceinline__ void mma_tf32(float* c, const uint32_t* a,
                                                uint32_t b0, uint32_t b1) {
    asm volatile(
        "mma.sync.aligned.m16n8k8.row.col.f32.tf32.tf32.f32 "
        "{%0,%1,%2,%3}, {%4,%5,%6,%7}, {%8,%9}, {%0,%1,%2,%3};"
        : "+f"(c[0]), "+f"(c[1]), "+f"(c[2]), "+f"(c[3])
        : "r"(a[0]), "r"(a[1]), "r"(a[2]), "r"(a[3]), "r"(b0), "r"(b1));
}
static __device__ __forceinline__ void cp16(float* s, const float* g) {
    uint32_t sa = (uint32_t)__cvta_generic_to_shared(s);
    asm volatile("cp.async.ca.shared.global [%0], [%1], 16;" :: "r"(sa), "l"(g));
}
#define CP_COMMIT() asm volatile("cp.async.commit_group;" ::: "memory")
#define CP_WAIT0()  asm volatile("cp.async.wait_group 0;" ::: "memory")
#define CP_WAIT1()  asm volatile("cp.async.wait_group 1;" ::: "memory")

// ---------------------------------------------------------------------------
// k_prep: tf32-round weights + zero g_deg (merged)
__global__ void k_prep(const float* __restrict__ Wn1, const float* __restrict__ Wn2,
                       const float* __restrict__ W0, const float* __restrict__ W1,
                       const float* __restrict__ Wh, int N) {
    int i = blockIdx.x * 256 + threadIdx.x;
    if (i < 24576)      ((float4*)g_wn1r)[i] = tf32r4(__ldg((const float4*)Wn1 + i));
    else if (i < 40960) ((float4*)g_wn2r)[i - 24576] = tf32r4(__ldg((const float4*)Wn2 + (i - 24576)));
    else if (i < 43008) ((float4*)g_wur)[i - 40960] = tf32r4(__ldg((const float4*)W0 + (i - 40960)));
    else if (i < 45056) ((float4*)g_wur)[i - 40960] = tf32r4(__ldg((const float4*)W1 + (i - 43008)));
    else if (i < 47104) ((float4*)g_wur)[i - 40960] = tf32r4(__ldg((const float4*)Wh + (i - 45056)));
    if (i < N) g_deg[i] = 0;
}

// ---------------------------------------------------------------------------
// _x = x @ W_down + b_down.  16 rows/block, 256 thr.
__global__ void k_down(const float* __restrict__ x, const float* __restrict__ Wd,
                       const float* __restrict__ bd, int N) {
    __shared__ float sX[16 * 256];
    int t = threadIdx.x;
    int row0 = blockIdx.x * 16;
    const float4* x4 = (const float4*)x + (size_t)row0 * 64;
    int lim = (N - row0) * 64;
    for (int idx = t; idx < 1024; idx += 256)
        ((float4*)sX)[idx] = (idx < lim) ? x4[idx] : make_float4(0.f, 0.f, 0.f, 0.f);
    __syncthreads();
    int cg = t & 15, rl = t >> 4;
    int row = row0 + rl;
    if (row >= N) return;
    float4 acc = *(const float4*)(bd + cg * 4);
    const float* xr = sX + rl * 256;
#pragma unroll 8
    for (int k = 0; k < 256; k++) {
        float4 w = __ldg((const float4*)(Wd + k * 64) + cg);
        acc = f4fma(xr[k], w, acc);
    }
    *(float4*)(g_x + (size_t)row * 64 + cg * 4) = acc;
}

// ---------------------------------------------------------------------------
__global__ void k_hist(const int* __restrict__ iv, int E) {
    int e = blockIdx.x * blockDim.x + threadIdx.x;
    if (e < E) atomicAdd(&g_deg[iv[e]], 1);
}

// single-block scan, smem-staged
__global__ void k_scan(int N) {
    extern __shared__ int si[];
    int* sDeg = si;
    int* sOff = si + N;
    __shared__ int warpTot[32];
    int t = threadIdx.x;
    for (int idx = t; idx < N; idx += 1024) sDeg[idx] = g_deg[idx];
    __syncthreads();
    int chunk = (N + 1023) >> 10;
    int base = t * chunk;
    int s = 0;
    for (int k = 0; k < chunk; k++) {
        int i = base + k;
        if (i < N) s += sDeg[i];
    }
    int lane = t & 31, w = t >> 5;
    int pre = s;
#pragma unroll
    for (int o = 1; o < 32; o <<= 1) {
        int u = __shfl_up_sync(0xffffffffu, pre, o);
        if (lane >= o) pre += u;
    }
    if (lane == 31) warpTot[w] = pre;
    __syncthreads();
    if (w == 0) {
        int v = warpTot[lane];
#pragma unroll
        for (int o = 1; o < 32; o <<= 1) {
            int u = __shfl_up_sync(0xffffffffu, v, o);
            if (lane >= o) v += u;
        }
        warpTot[lane] = v;
    }
    __syncthreads();
    int excl = pre - s + (w ? warpTot[w - 1] : 0);
    for (int k = 0; k < chunk; k++) {
        int i = base + k;
        if (i < N) { sOff[i] = excl; excl += sDeg[i]; }
    }
    __syncthreads();
    for (int idx = t; idx < N; idx += 1024) {
        int v = sOff[idx];
        g_off[idx] = v;
        g_cur[idx] = v;
    }
    if (t == 1023) g_off[N] = excl;
}

// ticket scatter: packed edge record at CSR position
__global__ void k_scatter(const int* __restrict__ iv, const int* __restrict__ jv,
                          const float* __restrict__ factor,
                          const float* __restrict__ sph0, const float* __restrict__ sph1,
                          int E) {
    int e = blockIdx.x * blockDim.x + threadIdx.x;
    if (e >= E) return;
    int i = iv[e];
    int pos = atomicAdd(&g_cur[i], 1);
    float4 A, B, C;
    A.x = __int_as_float(jv[e]);
    A.y = __int_as_float(e);
    A.z = __ldg(factor + e);
    A.w = __ldg(sph1 + (size_t)e * 3 + 0);
    B.x = __ldg(sph1 + (size_t)e * 3 + 1);
    B.y = __ldg(sph1 + (size_t)e * 3 + 2);
    B.z = __ldg(sph0 + (size_t)e * 5 + 0);
    B.w = __ldg(sph0 + (size_t)e * 5 + 1);
    C.x = __ldg(sph0 + (size_t)e * 5 + 2);
    C.y = __ldg(sph0 + (size_t)e * 5 + 3);
    C.z = __ldg(sph0 + (size_t)e * 5 + 4);
    C.w = 0.f;
    g_pack[(size_t)pos * 3 + 0] = A;
    g_pack[(size_t)pos * 3 + 1] = B;
    g_pack[(size_t)pos * 3 + 2] = C;
}

// ---------------------------------------------------------------------------
// gather: warp per node; software-pipelined (edge k+1 loads overlap edge k fma)
__global__ void __launch_bounds__(256) k_gather(const float* __restrict__ rbf, int N) {
    int w = (blockIdx.x * blockDim.x + threadIdx.x) >> 5;
    if (w >= N) return;
    int lane = threadIdx.x & 31;
    float2 acc[9];
#pragma unroll
    for (int c = 0; c < 9; c++) acc[c] = make_float2(0.f, 0.f);
    int k = g_off[w], kend = g_off[w + 1];

    float4 A, B, C;
    float2 xj = make_float2(0.f, 0.f), rb = make_float2(0.f, 0.f);
    A = make_float4(0.f, 0.f, 0.f, 0.f); B = A; C = A;
    if (k < kend) {
        A = g_pack[(size_t)k * 3 + 0];
        B = g_pack[(size_t)k * 3 + 1];
        C = g_pack[(size_t)k * 3 + 2];
        int j = __float_as_int(A.x);
        int e = __float_as_int(A.y);
        xj = *(const float2*)(g_x + (size_t)j * 64 + lane * 2);
        rb = __ldg((const float2*)(rbf + (size_t)e * 64) + lane);
    }
    while (k < kend) {
        // issue next edge's loads before consuming current
        float4 An = make_float4(0.f, 0.f, 0.f, 0.f), Bn = An, Cn = An;
        float2 xjn = make_float2(0.f, 0.f), rbn = xjn;
        int kn = k + 1;
        if (kn < kend) {
            An = g_pack[(size_t)kn * 3 + 0];
            Bn = g_pack[(size_t)kn * 3 + 1];
            Cn = g_pack[(size_t)kn * 3 + 2];
            int jn = __float_as_int(An.x);
            int en = __float_as_int(An.y);
            xjn = *(const float2*)(g_x + (size_t)jn * 64 + lane * 2);
            rbn = __ldg((const float2*)(rbf + (size_t)en * 64) + lane);
        }
        float l0x = xj.x * rb.x * A.z;
        float l0y = xj.y * rb.y * A.z;
        acc[0].x += l0x;                      acc[0].y += l0y;
        acc[1].x = fmaf(A.w, l0x, acc[1].x);  acc[1].y = fmaf(A.w, l0y, acc[1].y);
        acc[2].x = fmaf(B.x, l0x, acc[2].x);  acc[2].y = fmaf(B.x, l0y, acc[2].y);
        acc[3].x = fmaf(B.y, l0x, acc[3].x);  acc[3].y = fmaf(B.y, l0y, acc[3].y);
        acc[4].x = fmaf(B.z, l0x, acc[4].x);  acc[4].y = fmaf(B.z, l0y, acc[4].y);
        acc[5].x = fmaf(B.w, l0x, acc[5].x);  acc[5].y = fmaf(B.w, l0y, acc[5].y);
        acc[6].x = fmaf(C.x, l0x, acc[6].x);  acc[6].y = fmaf(C.x, l0y, acc[6].y);
        acc[7].x = fmaf(C.y, l0x, acc[7].x);  acc[7].y = fmaf(C.y, l0y, acc[7].y);
        acc[8].x = fmaf(C.z, l0x, acc[8].x);  acc[8].y = fmaf(C.z, l0y, acc[8].y);
        A = An; B = Bn; C = Cn; xj = xjn; rb = rbn;
        k = kn;
    }
    float2 xv = *(const float2*)(g_x + (size_t)w * 64 + lane * 2);
    float* base = g_agg + (size_t)w * 576 + lane * 2;
#pragma unroll
    for (int c = 0; c < 9; c++) {
        float2 v;
        v.x = tf32r(acc[c].x * xv.x);
        v.y = tf32r(acc[c].y * xv.y);
        *(float2*)(base + c * 64) = v;
    }
}

// ---------------------------------------------------------------------------
// k_up_mma: tf32 mma. 64 nodes/block, blockIdx.y = matrix m.
#define SV_S 68
#define SU_S 136
__global__ void __launch_bounds__(256) k_up_mma(const float* __restrict__ b0, int N) {
    extern __shared__ float sm[];
    float* sW = sm;               // 64*136 = 8704
    float* sV[2] = { sm + 8704, sm + 8704 + 4352 };
    int t = threadIdx.x, lane = t & 31, wid = t >> 5;
    int wm = wid & 1, wn = wid >> 1;
    int qr = lane >> 2, qc = lane & 3;
    int m = blockIdx.y;
    int tile0 = blockIdx.x * 64;

    int chBase = (m == 0) ? 0 : (m == 1) ? 1 : 4;
    int nch    = (m == 0) ? 1 : (m == 1) ? 3 : 5;

    {
        const float* Wg = g_wur + m * 8192;
#pragma unroll
        for (int i = 0; i < 8; i++) {
            int idx = t + i * 256;
            int r = idx >> 5, c4 = (idx & 31) * 4;
            cp16(sW + r * SU_S + c4, Wg + r * 128 + c4);
        }
#pragma unroll
        for (int i = 0; i < 4; i++) {
            int idx = t + i * 256;
            int r = idx >> 4, c4 = (idx & 15) * 4;
            cp16(sV[0] + r * SV_S + c4,
                 g_agg + (size_t)(tile0 + r) * 576 + chBase * 64 + c4);
        }
        CP_COMMIT();
    }

    float facc[2][4][4];
#pragma unroll
    for (int mt = 0; mt < 2; mt++)
#pragma unroll
        for (int nt = 0; nt < 4; nt++)
#pragma unroll
            for (int q = 0; q < 4; q++) facc[mt][nt][q] = 0.f;

    for (int ch = 0; ch < nch; ch++) {
        if (ch + 1 < nch) {
#pragma unroll
            for (int i = 0; i < 4; i++) {
                int idx = t + i * 256;
                int r = idx >> 4, c4 = (idx & 15) * 4;
                cp16(sV[(ch + 1) & 1] + r * SV_S + c4,
                     g_agg + (size_t)(tile0 + r) * 576 + (chBase + ch + 1) * 64 + c4);
            }
            CP_COMMIT();
            CP_WAIT1();
        } else {
            CP_WAIT0();
        }
        __syncthreads();
        const float* V = sV[ch & 1];

        float acc[2][4][4];
#pragma unroll
        for (int mt = 0; mt < 2; mt++)
#pragma unroll
            for (int nt = 0; nt < 4; nt++)
#pragma unroll
                for (int q = 0; q < 4; q++) acc[mt][nt][q] = 0.f;

#pragma unroll
        for (int k8 = 0; k8 < 8; k8++) {
            int kb = k8 * 8;
            uint32_t a[2][4];
#pragma unroll
            for (int mt = 0; mt < 2; mt++) {
                const uint32_t* p = (const uint32_t*)V +
                    (wm * 32 + mt * 16 + qr) * SV_S + kb + qc;
                a[mt][0] = p[0]; a[mt][2] = p[4];
                a[mt][1] = p[8 * SV_S]; a[mt][3] = p[8 * SV_S + 4];
            }
#pragma unroll
            for (int nt = 0; nt < 4; nt++) {
                const uint32_t* p = (const uint32_t*)sW +
                    (kb + qc) * SU_S + wn * 32 + nt * 8 + qr;
                uint32_t b0v = p[0], b1v = p[4 * SU_S];
                mma_tf32(acc[0][nt], a[0], b0v, b1v);
                mma_tf32(acc[1][nt], a[1], b0v, b1v);
            }
        }
        if (m == 0) {
#pragma unroll
            for (int mt = 0; mt < 2; mt++)
#pragma unroll
                for (int nt = 0; nt < 4; nt++)
#pragma unroll
                    for (int q = 0; q < 4; q++) facc[mt][nt][q] = acc[mt][nt][q];
        } else {
#pragma unroll
            for (int mt = 0; mt < 2; mt++)
#pragma unroll
                for (int nt = 0; nt < 4; nt++)
#pragma unroll
                    for (int q = 0; q < 4; q++)
                        facc[mt][nt][q] = fmaf(acc[mt][nt][q], acc[mt][nt][q], facc[mt][nt][q]);
        }
        __syncthreads();
    }

#pragma unroll
    for (int mt = 0; mt < 2; mt++) {
#pragma unroll
        for (int half = 0; half < 2; half++) {
            int n = tile0 + wm * 32 + mt * 16 + qr + half * 8;
            if (n < N) {
#pragma unroll
                for (int nt = 0; nt < 4; nt++) {
                    int c = wn * 32 + nt * 8 + qc * 2;
                    float2 o;
                    o.x = facc[mt][nt][half * 2 + 0];
                    o.y = facc[mt][nt][half * 2 + 1];
                    if (m == 0) { o.x += __ldg(b0 + c); o.y += __ldg(b0 + c + 1); }
                    o.x = tf32r(o.x); o.y = tf32r(o.y);
                    *(float2*)(g_node + (size_t)n * 384 + m * 128 + c) = o;
                }
            }
        }
    }
}

// ---------------------------------------------------------------------------
// k_mlp_mma: tf32 mma. 64 rows/block, 8 warps 2m x 4n, warp tile 32x64.
#define SN_S 388
#define SW_S 264
__global__ void __launch_bounds__(256) k_mlp_mma(
    const float* __restrict__ bn1, const float* __restrict__ lng,
    const float* __restrict__ lnb, const float* __restrict__ bn2,
    const float* __restrict__ x, float* __restrict__ out, int N) {
    extern __shared__ float sm[];
    float* sN = sm;                         // 64*388 = 24832
    float* sWb[2] = { sm + 24832, sm + 24832 + 8448 };  // each 32*264 = 8448
    float* sH = sm;                         // alias sN
    int t = threadIdx.x, lane = t & 31, wid = t >> 5;
    int wm = wid & 1, wn = wid >> 1;
    int row0 = blockIdx.x * 64;
    int qr = lane >> 2, qc = lane & 3;

    {
#pragma unroll
        for (int i = 0; i < 24; i++) {
            int idx = t + i * 256;
            int r = idx / 96, c4 = (idx - r * 96) * 4;
            cp16(sN + r * SN_S + c4, g_node + (size_t)(row0 + r) * 384 + c4);
        }
#pragma unroll
        for (int i = 0; i < 8; i++) {
            int idx = t + i * 256;
            int r = idx >> 6, c4 = (idx & 63) * 4;
            cp16(sWb[0] + r * SW_S + c4, g_wn1r + (size_t)r * 256 + c4);
        }
        CP_COMMIT();
    }

    float acc[2][8][4];
#pragma unroll
    for (int mt = 0; mt < 2; mt++)
#pragma unroll
        for (int nt = 0; nt < 8; nt++)
#pragma unroll
            for (int q = 0; q < 4; q++) acc[mt][nt][q] = 0.f;

    for (int kc = 0; kc < 12; kc++) {
        if (kc + 1 < 12) {
#pragma unroll
            for (int i = 0; i < 8; i++) {
                int idx = t + i * 256;
                int r = idx >> 6, c4 = (idx & 63) * 4;
                cp16(sWb[(kc + 1) & 1] + r * SW_S + c4,
                     g_wn1r + (size_t)((kc + 1) * 32 + r) * 256 + c4);
            }
            CP_COMMIT();
            CP_WAIT1();
        } else {
            CP_WAIT0();
        }
        __syncthreads();
        const float* sW = sWb[kc & 1];
#pragma unroll
        for (int k8 = 0; k8 < 4; k8++) {
            int kb = kc * 32 + k8 * 8;
            uint32_t a[2][4];
#pragma unroll
            for (int mt = 0; mt < 2; mt++) {
                const uint32_t* p = (const uint32_t*)sN +
                    (wm * 32 + mt * 16 + qr) * SN_S + kb + qc;
                a[mt][0] = p[0]; a[mt][2] = p[4];
                a[mt][1] = p[8 * SN_S]; a[mt][3] = p[8 * SN_S + 4];
            }
#pragma unroll
            for (int nt = 0; nt < 8; nt++) {
                const uint32_t* p = (const uint32_t*)sW +
                    (k8 * 8 + qc) * SW_S + wn * 64 + nt * 8 + qr;
                uint32_t b0 = p[0], b1 = p[4 * SW_S];
                mma_tf32(acc[0][nt], a[0], b0, b1);
                mma_tf32(acc[1][nt], a[1], b0, b1);
            }
        }
        __syncthreads();
    }

#pragma unroll
    for (int mt = 0; mt < 2; mt++)
#pragma unroll
        for (int nt = 0; nt < 8; nt++) {
            int r = wm * 32 + mt * 16 + qr;
            int c = wn * 64 + nt * 8 + qc * 2;
            *(float2*)(sH + r * SN_S + c) = make_float2(acc[mt][nt][0], acc[mt][nt][1]);
            *(float2*)(sH + (r + 8) * SN_S + c) = make_float2(acc[mt][nt][2], acc[mt][nt][3]);
        }
    __syncthreads();

#pragma unroll
    for (int rr = 0; rr < 8; rr++) {
        int r = wid * 8 + rr;
        float* hr = sH + r * SN_S;
        float vv[8];
        float s1 = 0.f, s2 = 0.f;
#pragma unroll
        for (int k2 = 0; k2 < 8; k2++) {
            int col = lane + 32 * k2;
            float v = hr[col] + __ldg(bn1 + col);
            vv[k2] = v; s1 += v; s2 = fmaf(v, v, s2);
        }
#pragma unroll
        for (int o = 16; o > 0; o >>= 1) {
            s1 += __shfl_xor_sync(0xffffffffu, s1, o);
            s2 += __shfl_xor_sync(0xffffffffu, s2, o);
        }
        float mean = s1 * (1.f / 256.f);
        float var = s2 * (1.f / 256.f) - mean * mean;
        float rstd = rsqrtf(var + 1e-5f);
#pragma unroll
        for (int k2 = 0; k2 < 8; k2++) {
            int col = lane + 32 * k2;
            float y = (vv[k2] - mean) * rstd * __ldg(lng + col) + __ldg(lnb + col);
            hr[col] = tf32r(y / (1.f + __expf(-y)));
        }
    }
    __syncthreads();

    {
#pragma unroll
        for (int i = 0; i < 8; i++) {
            int idx = t + i * 256;
            int r = idx >> 6, c4 = (idx & 63) * 4;
            cp16(sWb[0] + r * SW_S + c4, g_wn2r + (size_t)r * 256 + c4);
        }
        CP_COMMIT();
    }

#pragma unroll
    for (int mt = 0; mt < 2; mt++)
#pragma unroll
        for (int nt = 0; nt < 8; nt++)
#pragma unroll
            for (int q = 0; q < 4; q++) acc[mt][nt][q] = 0.f;

    for (int kc = 0; kc < 8; kc++) {
        if (kc + 1 < 8) {
#pragma unroll
            for (int i = 0; i < 8; i++) {
                int idx = t + i * 256;
                int r = idx >> 6, c4 = (idx & 63) * 4;
                cp16(sWb[(kc + 1) & 1] + r * SW_S + c4,
                     g_wn2r + (size_t)((kc + 1) * 32 + r) * 256 + c4);
            }
            CP_COMMIT();
            CP_WAIT1();
        } else {
            CP_WAIT0();
        }
        __syncthreads();
        const float* sW = sWb[kc & 1];
#pragma unroll
        for (int k8 = 0; k8 < 4; k8++) {
            int kb = kc * 32 + k8 * 8;
            uint32_t a[2][4];
#pragma unroll
            for (int mt = 0; mt < 2; mt++) {
                const uint32_t* p = (const uint32_t*)sH +
                    (wm * 32 + mt * 16 + qr) * SN_S + kb + qc;
                a[mt][0] = p[0]; a[mt][2] = p[4];
                a[mt][1] = p[8 * SN_S]; a[mt][3] = p[8 * SN_S + 4];
            }
#pragma unroll
            for (int nt = 0; nt < 8; nt++) {
                const uint32_t* p = (const uint32_t*)sW +
                    (k8 * 8 + qc) * SW_S + wn * 64 + nt * 8 + qr;
                uint32_t b0 = p[0], b1 = p[4 * SW_S];
                mma_tf32(acc[0][nt], a[0], b0, b1);
                mma_tf32(acc[1][nt], a[1], b0, b1);
            }
        }
        __syncthreads();
    }

#pragma unroll
    for (int mt = 0; mt < 2; mt++) {
        int rl = wm * 32 + mt * 16 + qr;
#pragma unroll
        for (int half = 0; half < 2; half++) {
            int rg = row0 + rl + half * 8;
            if (rg < N) {
#pragma unroll
                for (int nt = 0; nt < 8; nt++) {
                    int c = wn * 64 + nt * 8 + qc * 2;
                    float2 xv = __ldg((const float2*)(x + (size_t)rg * 256 + c));
                    float2 o;
                    o.x = acc[mt][nt][half * 2 + 0] + __ldg(bn2 + c) + xv.x;
                    o.y = acc[mt][nt][half * 2 + 1] + __ldg(bn2 + c + 1) + xv.y;
                    *(float2*)(out + (size_t)rg * 256 + c) = o;
                }
            }
        }
    }
}

// ---------------------------------------------------------------------------
extern "C" void kernel_launch(void* const* d_in, const int* in_sizes, int n_in,
                              void* d_out, int out_size) {
    const float* x      = (const float*)d_in[0];
    const float* rbf    = (const float*)d_in[1];
    const float* factor = (const float*)d_in[2];
    const float* sph0   = (const float*)d_in[3];
    const float* sph1   = (const float*)d_in[4];
    const float* Wd     = (const float*)d_in[5];
    const float* bd     = (const float*)d_in[6];
    const float* Wu0    = (const float*)d_in[7];
    const float* bu0    = (const float*)d_in[8];
    const float* Wu1    = (const float*)d_in[9];
    const float* Wuh    = (const float*)d_in[10];
    const float* Wn1    = (const float*)d_in[11];
    const float* bn1    = (const float*)d_in[12];
    const float* lng    = (const float*)d_in[13];
    const float* lnb    = (const float*)d_in[14];
    const float* Wn2    = (const float*)d_in[15];
    const float* bn2    = (const float*)d_in[16];
    const int*   jv     = (const int*)d_in[17];
    const int*   iv     = (const int*)d_in[18];
    float* out = (float*)d_out;

    int N = in_sizes[0] / 256;
    int E = in_sizes[17];

    int mlpSmem = (24832 + 2 * 8448) * 4;   // 167,680 B
    int upSmem  = (8704 + 2 * 4352) * 4;    // 69,632 B
    cudaFuncSetAttribute(k_up_mma,  cudaFuncAttributeMaxDynamicSharedMemorySize, upSmem);
    cudaFuncSetAttribute(k_scan,    cudaFuncAttributeMaxDynamicSharedMemorySize, 2 * (N + 4) * 4);
    cudaFuncSetAttribute(k_mlp_mma, cudaFuncAttributeMaxDynamicSharedMemorySize, mlpSmem);

    k_prep<<<184, 256>>>(Wn1, Wn2, Wu0, Wu1, Wuh, N);
    k_down<<<(N + 15) / 16, 256>>>(x, Wd, bd, N);
    k_hist<<<(E + 255) / 256, 256>>>(iv, E);
    k_scan<<<1, 1024, 2 * (N + 4) * 4>>>(N);
    k_scatter<<<(E + 255) / 256, 256>>>(iv, jv, factor, sph0, sph1, E);
    k_gather<<<(N + 7) / 8, 256>>>(rbf, N);
    dim3 upGrid((N + 63) / 64, 3);
    k_up_mma<<<upGrid, 256, upSmem>>>(bu0, N);
    k_mlp_mma<<<(N + 63) / 64, 256, mlpSmem>>>(bn1, lng, lnb, bn2, x, out, N);
}